// round 13
// baseline (speedup 1.0000x reference)
#include <cuda_runtime.h>
#include <cuda_bf16.h>
#include <math.h>
#include <stdint.h>

// ---------------- problem constants ----------------
#define BQ    256        // batch
#define SQ    20         // seq len
#define EDIM  128        // embedding dim
#define HDIM  256        // lstm hidden
#define G4    1024       // 4*H
#define H16   4096       // 16*H
#define TOT   2768       // hypernet output width
#define IMG   64
#define FLAT  65536      // 16*64*64
#define SLOPE (1.0f/5.5f)

// ---------------- device scratch (static, no allocs) ----------------
__device__ float d_Xg[SQ*BQ*G4];
__device__ float d_whhT[HDIM*G4];
__device__ float d_hbuf[2][BQ*HDIM];
__device__ float d_h1[BQ*G4];
__device__ float d_allw[BQ*TOT];
__device__ float d_conv1o[BQ*16*IMG*IMG];
// bf16 operands
__device__ __nv_bfloat16 d_Xehl[SQ*BQ*384];     // [Ah|Al|Ah] for Xg gemm
__device__ __nv_bfloat16 d_Bwih[G4*384];        // [Bh|Bh|Bl] of w_ih
__device__ __nv_bfloat16 d_Ahi[BQ*FLAT];        // fc1 A hi (written by conv2)
__device__ __nv_bfloat16 d_Alo[BQ*FLAT];
__device__ __nv_bfloat16 d_Bthi[512*FLAT];      // lw1^T  (512 x 65536)
__device__ __nv_bfloat16 d_Btlo[512*FLAT];
__device__ __nv_bfloat16 d_Bt2hi[H16*G4];       // hw2^T  (4096 x 1024)
__device__ __nv_bfloat16 d_Bt2lo[H16*G4];
__device__ __nv_bfloat16 d_Bt3hi[TOT*H16];      // hw3^T  (2768 x 4096)
__device__ __nv_bfloat16 d_Bt3lo[TOT*H16];
__device__ __nv_bfloat16 d_h1hi[BQ*G4];
__device__ __nv_bfloat16 d_h1lo[BQ*G4];
__device__ __nv_bfloat16 d_h2hi[BQ*H16];
__device__ __nv_bfloat16 d_h2lo[BQ*H16];
// shared split-K partial buffer (sequentially reused by hw2, hw3, fc1)
#define GPART_ELEMS (8*256*4096)                // 33.5 MB
__device__ float d_gpart[GPART_ELEMS];
__device__ float d_fc1[BQ*512];
// persistent-LSTM grid barrier state
__device__ unsigned d_barc = 0;
__device__ unsigned d_barg = 0;

__device__ __forceinline__ float sigmoidf_(float x) { return 1.0f / (1.0f + expf(-x)); }

__device__ __forceinline__ uint32_t smem_u32(const void* p) {
    uint32_t a;
    asm("{ .reg .u64 t; cvta.to.shared.u64 t, %1; cvt.u32.u64 %0, t; }" : "=r"(a) : "l"(p));
    return a;
}

// ---------------- input conversion kernels ----------------
__global__ void gather_hl_kernel(const int* __restrict__ q, const float* __restrict__ emb) {
    int idx = blockIdx.x * 256 + threadIdx.x;
    if (idx < SQ*BQ*EDIM) {
        int e = idx & 127, m = idx >> 7;
        int tt = m / BQ, bb = m % BQ;
        float v = emb[(size_t)q[bb*SQ + tt] * EDIM + e];
        __nv_bfloat16 h = __float2bfloat16(v);
        __nv_bfloat16 l = __float2bfloat16(v - __bfloat162float(h));
        d_Xehl[(size_t)m*384 + e]       = h;
        d_Xehl[(size_t)m*384 + 128 + e] = l;
        d_Xehl[(size_t)m*384 + 256 + e] = h;
    }
}

__global__ void convert_wih_kernel(const float* __restrict__ w_ih) {
    int i = blockIdx.x * 256 + threadIdx.x;    // 131072
    int n = i >> 7, k = i & 127;
    float v = w_ih[i];
    __nv_bfloat16 h = __float2bfloat16(v);
    __nv_bfloat16 l = __float2bfloat16(v - __bfloat162float(h));
    d_Bwih[(size_t)n*384 + k]       = h;
    d_Bwih[(size_t)n*384 + 128 + k] = h;
    d_Bwih[(size_t)n*384 + 256 + k] = l;
}

__global__ void transpose_kernel(const float* __restrict__ src, float* __restrict__ dst,
                                 int R, int C) {
    int i = blockIdx.x * 256 + threadIdx.x;
    if (i < R*C) { int r = i / C, c = i % C; dst[(size_t)c*R + r] = src[i]; }
}

__global__ void convert_hilo_kernel(const float* __restrict__ src,
                                    __nv_bfloat16* __restrict__ hi,
                                    __nv_bfloat16* __restrict__ lo) {
    size_t i = ((size_t)blockIdx.x * 256 + threadIdx.x) * 4;
    float4 v = *(const float4*)(src + i);
    float vv[4] = {v.x, v.y, v.z, v.w};
    __nv_bfloat16 h[4], l[4];
#pragma unroll
    for (int j = 0; j < 4; j++) {
        h[j] = __float2bfloat16(vv[j]);
        l[j] = __float2bfloat16(vv[j] - __bfloat162float(h[j]));
    }
    __nv_bfloat162* ph = (__nv_bfloat162*)(hi + i);
    __nv_bfloat162* pl = (__nv_bfloat162*)(lo + i);
    ph[0] = __nv_bfloat162{h[0], h[1]}; ph[1] = __nv_bfloat162{h[2], h[3]};
    pl[0] = __nv_bfloat162{l[0], l[1]}; pl[1] = __nv_bfloat162{l[2], l[3]};
}

__global__ void transconv_kernel(const float* __restrict__ src,
                                 __nv_bfloat16* __restrict__ dsthi,
                                 __nv_bfloat16* __restrict__ dstlo, int K, int N) {
    __shared__ float t[32][33];
    const int k0 = blockIdx.x * 32;
    const int n0 = blockIdx.y * 32;
    const int tx = threadIdx.x & 31, ty = threadIdx.x >> 5;
    for (int r = ty; r < 32; r += 8) {
        int n = n0 + tx;
        t[r][tx] = (n < N) ? src[(size_t)(k0 + r) * N + n] : 0.0f;
    }
    __syncthreads();
    for (int r = ty; r < 32; r += 8) {
        if (n0 + r < N) {
            float x = t[tx][r];
            __nv_bfloat16 h = __float2bfloat16(x);
            __nv_bfloat16 l = __float2bfloat16(x - __bfloat162float(h));
            size_t o = (size_t)(n0 + r) * K + k0 + tx;
            dsthi[o] = h;
            dstlo[o] = l;
        }
    }
}

// ---------------- generic fp32 GEMM (used for hw1 only) ----------------
template<int ACT, bool BIAS2>
__global__ void gemm_nn_kernel(const float* __restrict__ A, const float* __restrict__ B,
                               const float* __restrict__ bias, const float* __restrict__ bias2,
                               float* __restrict__ C, int M, int N, int K) {
    __shared__ float As[16][68];
    __shared__ float Bs[16][64];
    const int tid = threadIdx.x;
    const int m0 = blockIdx.y * 64;
    const int n0 = blockIdx.x * 64;
    const int ty = tid >> 4, tx = tid & 15;
    const int ar = tid >> 2, ac = (tid & 3) << 2;
    const int br = tid >> 4, bc = (tid & 15) << 2;

    float acc[4][4];
#pragma unroll
    for (int i = 0; i < 4; i++)
#pragma unroll
        for (int j = 0; j < 4; j++) acc[i][j] = 0.0f;

    for (int k0 = 0; k0 < K; k0 += 16) {
        float4 av = *(const float4*)(A + (size_t)(m0 + ar) * K + k0 + ac);
        As[ac+0][ar] = av.x; As[ac+1][ar] = av.y; As[ac+2][ar] = av.z; As[ac+3][ar] = av.w;
        float4 bv = *(const float4*)(B + (size_t)(k0 + br) * N + n0 + bc);
        *(float4*)&Bs[br][bc] = bv;
        __syncthreads();
#pragma unroll
        for (int k = 0; k < 16; k++) {
            float a0 = As[k][ty*4+0], a1 = As[k][ty*4+1];
            float a2 = As[k][ty*4+2], a3 = As[k][ty*4+3];
            float4 b4 = *(const float4*)&Bs[k][tx*4];
            acc[0][0] += a0*b4.x; acc[0][1] += a0*b4.y; acc[0][2] += a0*b4.z; acc[0][3] += a0*b4.w;
            acc[1][0] += a1*b4.x; acc[1][1] += a1*b4.y; acc[1][2] += a1*b4.z; acc[1][3] += a1*b4.w;
            acc[2][0] += a2*b4.x; acc[2][1] += a2*b4.y; acc[2][2] += a2*b4.z; acc[2][3] += a2*b4.w;
            acc[3][0] += a3*b4.x; acc[3][1] += a3*b4.y; acc[3][2] += a3*b4.z; acc[3][3] += a3*b4.w;
        }
        __syncthreads();
    }

#pragma unroll
    for (int i = 0; i < 4; i++) {
        int row = m0 + ty*4 + i;
#pragma unroll
        for (int j = 0; j < 4; j++) {
            int col = n0 + tx*4 + j;
            float v = acc[i][j] + bias[col];
            if (BIAS2) v += bias2[col];
            if (ACT == 1) v = (v > 0.0f) ? v : v * SLOPE;
            else if (ACT == 2) v = fmaxf(v, 0.0f);
            C[(size_t)row * N + col] = v;
        }
    }
}

// ---------------- unified HMMA GEMM (2-stage pipeline, 2 CTAs/SM, fused phases) ----------------
// blockIdx.z = pure K-slice. Inside, loops nphase phases accumulating into the
// SAME registers: partial_z = sum_ph A_ph[m,kslice] @ B_ph[n,kslice]^T.
//   Cpart != nullptr: write fp32 partials [z][M x N]
//   Cpart == nullptr: write Cout = acc + bias (+bias2)
#define TILE_E 9216   // 128*72 bf16 elements per tile
#define STAGE_E (2*TILE_E)
__device__ __forceinline__ void g2s_stage(
    const __nv_bfloat16* __restrict__ Aptr, const __nv_bfloat16* __restrict__ Bptr,
    __nv_bfloat16* sA, __nv_bfloat16* sB,
    int tid, int m0, int n0, int N, size_t K, size_t k0) {
#pragma unroll
    for (int c8 = 0; c8 < 8; c8++) {
        int c = tid + (c8 << 8);
        int r = (c & 1023) >> 3, kc = (c & 7) << 3;
        if (c < 1024) {
            const void* g = Aptr + (size_t)(m0 + r) * K + k0 + kc;
            uint32_t s = smem_u32(sA + r * 72 + kc);
            asm volatile("cp.async.cg.shared.global [%0], [%1], 16;" :: "r"(s), "l"(g));
        } else {
            int valid = (n0 + r) < N;
            const void* g = Bptr + (valid ? ((size_t)(n0 + r) * K + k0 + kc) : 0);
            uint32_t s = smem_u32(sB + r * 72 + kc);
            int sz = valid ? 16 : 0;
            asm volatile("cp.async.cg.shared.global [%0], [%1], 16, %2;" :: "r"(s), "l"(g), "r"(sz));
        }
    }
}

__global__ __launch_bounds__(256, 2) void gemm_mma_splitk(
    const __nv_bfloat16* __restrict__ Ahi, const __nv_bfloat16* __restrict__ Alo,
    const __nv_bfloat16* __restrict__ Bthi, const __nv_bfloat16* __restrict__ Btlo,
    float* __restrict__ Cpart, int N, int K, int kchunk, int nphase,
    const float* __restrict__ bias, const float* __restrict__ bias2,
    float* __restrict__ Cout) {
    extern __shared__ __nv_bfloat16 sm[];

    const int tid  = threadIdx.x;
    const int warp = tid >> 5, lane = tid & 31;
    const int n0 = blockIdx.x * 128;
    const int m0 = blockIdx.y * 128;
    const int M  = gridDim.y * 128;
    const int z  = blockIdx.z;
    const size_t kbase = (size_t)z * kchunk;
    const int iters = kchunk >> 6;
    const int total = nphase * iters;

    const __nv_bfloat16* Ap[3] = {Ahi, Alo, Ahi};
    const __nv_bfloat16* Bp[3] = {Bthi, Bthi, Btlo};

    const int wm = warp >> 2;
    const int wn = warp & 3;
    const int g  = lane >> 2, tig = lane & 3;

    float acc[4][4][4];
#pragma unroll
    for (int mt = 0; mt < 4; mt++)
#pragma unroll
        for (int nt = 0; nt < 4; nt++)
#pragma unroll
            for (int e = 0; e < 4; e++) acc[mt][nt][e] = 0.0f;

    const int a_row = (lane & 15);
    const int a_kad = (lane >> 4) * 8;
    const int b_row = (lane >> 4) * 8 + (lane & 7);
    const int b_kad = ((lane >> 3) & 1) * 8;

    // prologue: fetch iteration 0 into stage 0
    g2s_stage(Ap[0], Bp[0], sm, sm + TILE_E, tid, m0, n0, N, K, kbase);
    asm volatile("cp.async.commit_group;" ::: "memory");

    for (int j = 0; j < total; ++j) {
        if (j + 1 < total) {
            int jn = j + 1;
            int ph = jn / iters, itk = jn - ph * iters;
            const int st2 = jn & 1;
            g2s_stage(Ap[ph], Bp[ph], sm + st2 * STAGE_E, sm + st2 * STAGE_E + TILE_E,
                      tid, m0, n0, N, K, kbase + (size_t)itk * 64);
        }
        asm volatile("cp.async.commit_group;" ::: "memory");
        asm volatile("cp.async.wait_group 1;" ::: "memory");
        __syncthreads();

        const uint32_t sAb = smem_u32(sm) + (j & 1) * (STAGE_E * 2);
        const uint32_t sBb = sAb + TILE_E * 2;

#pragma unroll
        for (int ks = 0; ks < 4; ks++) {
            uint32_t a[4][4];
#pragma unroll
            for (int mt = 0; mt < 4; mt++) {
                uint32_t addr = sAb + ((wm*64 + mt*16 + a_row) * 72 + ks*16 + a_kad) * 2;
                asm volatile("ldmatrix.sync.aligned.m8n8.x4.shared.b16 {%0,%1,%2,%3}, [%4];"
                    : "=r"(a[mt][0]), "=r"(a[mt][1]), "=r"(a[mt][2]), "=r"(a[mt][3])
                    : "r"(addr));
            }
            uint32_t b[4][2];
#pragma unroll
            for (int np = 0; np < 2; np++) {
                uint32_t addr = sBb + ((wn*32 + np*16 + b_row) * 72 + ks*16 + b_kad) * 2;
                uint32_t r0, r1, r2, r3;
                asm volatile("ldmatrix.sync.aligned.m8n8.x4.shared.b16 {%0,%1,%2,%3}, [%4];"
                    : "=r"(r0), "=r"(r1), "=r"(r2), "=r"(r3) : "r"(addr));
                b[np*2+0][0] = r0; b[np*2+0][1] = r1;
                b[np*2+1][0] = r2; b[np*2+1][1] = r3;
            }
#pragma unroll
            for (int mt = 0; mt < 4; mt++)
#pragma unroll
                for (int nt = 0; nt < 4; nt++) {
                    asm volatile(
                        "mma.sync.aligned.m16n8k16.row.col.f32.bf16.bf16.f32 "
                        "{%0,%1,%2,%3}, {%4,%5,%6,%7}, {%8,%9}, {%0,%1,%2,%3};"
                        : "+f"(acc[mt][nt][0]), "+f"(acc[mt][nt][1]),
                          "+f"(acc[mt][nt][2]), "+f"(acc[mt][nt][3])
                        : "r"(a[mt][0]), "r"(a[mt][1]), "r"(a[mt][2]), "r"(a[mt][3]),
                          "r"(b[nt][0]), "r"(b[nt][1]));
                }
        }
        __syncthreads();
    }

    if (Cpart) {
        float* outz = Cpart + (size_t)z * M * N;
#pragma unroll
        for (int mt = 0; mt < 4; mt++)
#pragma unroll
            for (int nt = 0; nt < 4; nt++) {
                int row0 = m0 + wm*64 + mt*16 + g;
                int col  = n0 + wn*32 + nt*8 + tig*2;
                if (col < N) {
                    *(float2*)(outz + (size_t)row0 * N + col)
                        = make_float2(acc[mt][nt][0], acc[mt][nt][1]);
                    *(float2*)(outz + (size_t)(row0 + 8) * N + col)
                        = make_float2(acc[mt][nt][2], acc[mt][nt][3]);
                }
            }
    } else {
#pragma unroll
        for (int mt = 0; mt < 4; mt++)
#pragma unroll
            for (int nt = 0; nt < 4; nt++) {
                int row0 = m0 + wm*64 + mt*16 + g;
                int col  = n0 + wn*32 + nt*8 + tig*2;
                if (col < N) {
                    float b0v = bias[col]   + (bias2 ? bias2[col]   : 0.0f);
                    float b1v = bias[col+1] + (bias2 ? bias2[col+1] : 0.0f);
                    *(float2*)(Cout + (size_t)row0 * N + col)
                        = make_float2(acc[mt][nt][0] + b0v, acc[mt][nt][1] + b1v);
                    *(float2*)(Cout + (size_t)(row0 + 8) * N + col)
                        = make_float2(acc[mt][nt][2] + b0v, acc[mt][nt][3] + b1v);
                }
            }
    }
}

// ---------------- split-K reduce kernels ----------------
__global__ void reduce_hw2_kernel(const float* __restrict__ hb2) {
    int i = blockIdx.x * 256 + threadIdx.x;
    float s = hb2[i & (H16-1)];
#pragma unroll
    for (int zz = 0; zz < 4; zz++) s += d_gpart[(size_t)zz * (BQ*H16) + i];
    s = (s > 0.0f) ? s : s * SLOPE;
    __nv_bfloat16 h = __float2bfloat16(s);
    d_h2hi[i] = h;
    d_h2lo[i] = __float2bfloat16(s - __bfloat162float(h));
}

__global__ void reduce_hw3_kernel(const float* __restrict__ hb3) {
    int i = blockIdx.x * 256 + threadIdx.x;
    int col = i % TOT;
    float s = hb3[col];
#pragma unroll
    for (int zz = 0; zz < 8; zz++) s += d_gpart[(size_t)zz * (BQ*TOT) + i];
    d_allw[i] = s;
}

__global__ void fc1_reduce_kernel(const float* __restrict__ lb1) {
    int i = blockIdx.x * 256 + threadIdx.x;
    float s = lb1[i & 511];
#pragma unroll
    for (int zz = 0; zz < 32; zz++) s += d_gpart[(size_t)zz * (BQ*512) + i];
    d_fc1[i] = s;
}

// ---------------- persistent fused LSTM (unchanged) ----------------
__global__ __launch_bounds__(128) void lstm_fused_kernel() {
    extern __shared__ float lsm[];
    float* ws = lsm;               // [256][64]
    float* hs = lsm + 256*64;      // [256][33]

    const int tid = threadIdx.x;
    const int u0 = blockIdx.x * 16;
    const int b0 = blockIdx.y * 32;
    const int tx = tid & 15;
    const int ty = tid >> 4;

    for (int e = tid; e < 16384; e += 128) {
        int kk = e >> 6, c = e & 63;
        int gg = c >> 4, uu = c & 15;
        ws[e] = d_whhT[(size_t)kk * G4 + gg * HDIM + u0 + uu];
    }

    float creg[4] = {0.f, 0.f, 0.f, 0.f};

    for (int t = 0; t < SQ; t++) {
        float acc[4][4];
#pragma unroll
        for (int bi = 0; bi < 4; bi++)
#pragma unroll
            for (int gg = 0; gg < 4; gg++) acc[bi][gg] = 0.0f;

        if (t > 0) {
            const float* hsrc = d_hbuf[(t-1) & 1];
            for (int e = tid; e < 8192; e += 128) {
                int bb = e >> 8, kk = e & 255;
                hs[kk*33 + bb] = __ldcg(&hsrc[(b0 + bb) * HDIM + kk]);
            }
            __syncthreads();
#pragma unroll 4
            for (int k = 0; k < 256; k++) {
                float w0 = ws[k*64 +      tx];
                float w1 = ws[k*64 + 16 + tx];
                float w2 = ws[k*64 + 32 + tx];
                float w3 = ws[k*64 + 48 + tx];
#pragma unroll
                for (int bi = 0; bi < 4; bi++) {
                    float h = hs[k*33 + ty*4 + bi];
                    acc[bi][0] += h * w0; acc[bi][1] += h * w1;
                    acc[bi][2] += h * w2; acc[bi][3] += h * w3;
                }
            }
        }

        float* hdst = d_hbuf[t & 1];
#pragma unroll
        for (int bi = 0; bi < 4; bi++) {
            int b = b0 + ty*4 + bi;
            const float* xg = d_Xg + ((size_t)t * BQ + b) * G4 + u0 + tx;
            float iv = sigmoidf_(acc[bi][0] + xg[0]);
            float fv = sigmoidf_(acc[bi][1] + xg[HDIM]);
            float gv = tanhf    (acc[bi][2] + xg[2*HDIM]);
            float ov = sigmoidf_(acc[bi][3] + xg[3*HDIM]);
            float c = fv * creg[bi] + iv * gv;
            creg[bi] = c;
            hdst[b * HDIM + u0 + tx] = ov * tanhf(c);
        }

        if (t < SQ - 1) {
            __syncthreads();
            __threadfence();
            if (tid == 0) {
                unsigned gen = atomicAdd(&d_barg, 0u);
                if (atomicAdd(&d_barc, 1u) == 127u) {
                    atomicExch(&d_barc, 0u);
                    __threadfence();
                    atomicExch(&d_barg, gen + 1u);
                } else {
                    while (atomicAdd(&d_barg, 0u) == gen) __nanosleep(64);
                }
                __threadfence();
            }
            __syncthreads();
        }
    }
}

// ---------------- conv1 (unchanged) ----------------
__global__ void conv1_kernel(const float* __restrict__ images) {
    extern __shared__ float smf[];
    float* sin = smf;
    float* sw  = smf + 3*4096;
    float* sb  = sw + 432;
    const int b = blockIdx.x;
    const int tid = threadIdx.x;

    const float* ip = images + (size_t)b * 3 * 4096;
    for (int i = tid; i < 3*4096; i += 256) sin[i] = ip[i];
    const float* wp = d_allw + (size_t)b * TOT;
    for (int i = tid; i < 448; i += 256) {
        if (i < 432) sw[i] = wp[i]; else sb[i-432] = wp[i];
    }
    __syncthreads();

    for (int task = tid; task < 16*64*4; task += 256) {
        int oc = task >> 8;
        int y  = (task >> 2) & 63;
        int x0 = (task & 3) << 4;
        float accs[16];
#pragma unroll
        for (int i = 0; i < 16; i++) accs[i] = 0.0f;

        for (int ic = 0; ic < 3; ic++) {
#pragma unroll
            for (int ky = 0; ky < 3; ky++) {
                int yy = y + ky - 1;
                if (yy < 0 || yy >= 64) continue;
                const float* row = sin + ic*4096 + yy*64;
                const float* w3  = sw + ((oc*3 + ic)*3 + ky)*3;
                float w0 = w3[0], w1 = w3[1], w2 = w3[2];
                float vals[18];
#pragma unroll
                for (int i = 0; i < 18; i++) {
                    int x = x0 + i - 1;
                    vals[i] = (x >= 0 && x < 64) ? row[x] : 0.0f;
                }
#pragma unroll
                for (int i = 0; i < 16; i++)
                    accs[i] += w0*vals[i] + w1*vals[i+1] + w2*vals[i+2];
            }
        }
        float bv = sb[oc];
        float* op = d_conv1o + (((size_t)b*16 + oc)*64 + y)*64 + x0;
#pragma unroll
        for (int i = 0; i < 16; i++) op[i] = accs[i] + bv;
    }
}

// ---------------- conv2: writes bf16 hi/lo directly (unchanged) ----------------
__global__ void conv2_kernel() {
    extern __shared__ float smf[];
    float* sin = smf;
    float* sw  = smf + 16*18*64;
    float* sb  = sw + 2304;
    const int b  = blockIdx.y;
    const int y0 = blockIdx.x * 16;
    const int tid = threadIdx.x;

    const float* ip = d_conv1o + (size_t)b * 16 * 4096;
    for (int i = tid; i < 16*18*64; i += 256) {
        int ic = i / (18*64);
        int r  = (i / 64) % 18;
        int x  = i & 63;
        int yy = y0 + r - 1;
        sin[i] = (yy >= 0 && yy < 64) ? ip[ic*4096 + yy*64 + x] : 0.0f;
    }
    const float* wp = d_allw + (size_t)b * TOT + 448;
    for (int i = tid; i < 2320; i += 256) {
        if (i < 2304) sw[i] = wp[i]; else sb[i-2304] = wp[i];
    }
    __syncthreads();

    const int pos = tid & 63;
    const int ocg = tid >> 6;
    const int y  = pos >> 2;
    const int x0 = (pos & 3) << 4;

    float acc[4][16];
#pragma unroll
    for (int o = 0; o < 4; o++)
#pragma unroll
        for (int i = 0; i < 16; i++) acc[o][i] = 0.0f;

    for (int ic = 0; ic < 16; ic++) {
#pragma unroll
        for (int ky = 0; ky < 3; ky++) {
            const float* row = sin + (ic*18 + y + ky) * 64;
            float w[4][3];
#pragma unroll
            for (int o = 0; o < 4; o++)
#pragma unroll
                for (int kx = 0; kx < 3; kx++)
                    w[o][kx] = sw[(((ocg*4 + o)*16 + ic)*3 + ky)*3 + kx];
            float vals[18];
#pragma unroll
            for (int i = 0; i < 18; i++) {
                int x = x0 + i - 1;
                vals[i] = (x >= 0 && x < 64) ? row[x] : 0.0f;
            }
#pragma unroll
            for (int o = 0; o < 4; o++)
#pragma unroll
                for (int i = 0; i < 16; i++)
                    acc[o][i] += w[o][0]*vals[i] + w[o][1]*vals[i+1] + w[o][2]*vals[i+2];
        }
    }
#pragma unroll
    for (int o = 0; o < 4; o++) {
        int oc = ocg*4 + o;
        float bv = sb[oc];
        size_t base = (((size_t)b*16 + oc)*64 + (y0 + y))*64 + x0;
#pragma unroll
        for (int i = 0; i < 16; i++) {
            float v = acc[o][i] + bv;
            __nv_bfloat16 h = __float2bfloat16(v);
            d_Ahi[base + i] = h;
            d_Alo[base + i] = __float2bfloat16(v - __bfloat162float(h));
        }
    }
}

// ---------------- fused fc2 + fc3 (unchanged) ----------------
__global__ void fc23_kernel(const float* __restrict__ lw2, const float* __restrict__ lb2,
                            const float* __restrict__ lw3, const float* __restrict__ lb3,
                            float* __restrict__ out) {
    const int b = blockIdx.x;
    const int j = threadIdx.x;
    const float* a = d_fc1 + (size_t)b * 512;
    float acc = lb2[j];
#pragma unroll 4
    for (int k = 0; k < 512; k++)
        acc += fmaxf(a[k], 0.0f) * lw2[(size_t)k*64 + j];
    acc = fmaxf(acc, 0.0f);
    __shared__ float h[64];
    h[j] = acc;
    __syncthreads();
    if (j < 2) {
        float s = lb3[j];
#pragma unroll
        for (int q = 0; q < 64; q++) s += h[q] * lw3[q*2 + j];
        out[b*2 + j] = s;
    }
}

// ---------------- launch ----------------
extern "C" void kernel_launch(void* const* d_in, const int* in_sizes, int n_in,
                              void* d_out, int out_size) {
    const int*   questions = (const int*)  d_in[0];
    const float* images    = (const float*)d_in[1];
    const float* emb       = (const float*)d_in[2];
    const float* w_ih      = (const float*)d_in[3];
    const float* w_hh      = (const float*)d_in[4];
    const float* b_ih      = (const float*)d_in[5];
    const float* b_hh      = (const float*)d_in[6];
    const float* hw1       = (const float*)d_in[7];
    const float* hb1       = (const float*)d_in[8];
    const float* hw2       = (const float*)d_in[9];
    const float* hb2       = (const float*)d_in[10];
    const float* hw3       = (const float*)d_in[11];
    const float* hb3       = (const float*)d_in[12];
    const float* lw1       = (const float*)d_in[13];
    const float* lb1       = (const float*)d_in[14];
    const float* lw2       = (const float*)d_in[15];
    const float* lb2       = (const float*)d_in[16];
    const float* lw3       = (const float*)d_in[17];
    const float* lb3       = (const float*)d_in[18];
    float* out = (float*)d_out;

    // __device__ symbols are NOT valid device pointers in host code: fetch real addresses.
    float *p_Xg, *p_whhT, *p_hbuf, *p_h1, *p_gpart;
    __nv_bfloat16 *p_Xehl, *p_Bwih, *p_Ahi, *p_Alo, *p_Bthi, *p_Btlo,
                  *p_Bt2hi, *p_Bt2lo, *p_Bt3hi, *p_Bt3lo,
                  *p_h1hi, *p_h1lo, *p_h2hi, *p_h2lo;
    cudaGetSymbolAddress((void**)&p_Xg,    d_Xg);
    cudaGetSymbolAddress((void**)&p_whhT,  d_whhT);
    cudaGetSymbolAddress((void**)&p_hbuf,  d_hbuf);
    cudaGetSymbolAddress((void**)&p_h1,    d_h1);
    cudaGetSymbolAddress((void**)&p_gpart, d_gpart);
    cudaGetSymbolAddress((void**)&p_Xehl,  d_Xehl);
    cudaGetSymbolAddress((void**)&p_Bwih,  d_Bwih);
    cudaGetSymbolAddress((void**)&p_Ahi,   d_Ahi);
    cudaGetSymbolAddress((void**)&p_Alo,   d_Alo);
    cudaGetSymbolAddress((void**)&p_Bthi,  d_Bthi);
    cudaGetSymbolAddress((void**)&p_Btlo,  d_Btlo);
    cudaGetSymbolAddress((void**)&p_Bt2hi, d_Bt2hi);
    cudaGetSymbolAddress((void**)&p_Bt2lo, d_Bt2lo);
    cudaGetSymbolAddress((void**)&p_Bt3hi, d_Bt3hi);
    cudaGetSymbolAddress((void**)&p_Bt3lo, d_Bt3lo);
    cudaGetSymbolAddress((void**)&p_h1hi,  d_h1hi);
    cudaGetSymbolAddress((void**)&p_h1lo,  d_h1lo);
    cudaGetSymbolAddress((void**)&p_h2hi,  d_h2hi);
    cudaGetSymbolAddress((void**)&p_h2lo,  d_h2lo);

    const int conv1_smem = (3*4096 + 448) * 4;
    const int conv2_smem = (16*18*64 + 2320) * 4;
    const int mma_smem   = 2 * STAGE_E * 2;          // 73728 B (2 stages -> 2 CTAs/SM)
    const int lstm_smem  = (16384 + 256*33) * 4;     // 99328 B
    cudaFuncSetAttribute(conv1_kernel, cudaFuncAttributeMaxDynamicSharedMemorySize, conv1_smem);
    cudaFuncSetAttribute(conv2_kernel, cudaFuncAttributeMaxDynamicSharedMemorySize, conv2_smem);
    cudaFuncSetAttribute(gemm_mma_splitk, cudaFuncAttributeMaxDynamicSharedMemorySize, mma_smem);
    cudaFuncSetAttribute(lstm_fused_kernel, cudaFuncAttributeMaxDynamicSharedMemorySize, lstm_smem);

    // 1) transpose w_hh (fp32, for LSTM smem)
    transpose_kernel<<<(G4*HDIM + 255)/256, 256>>>(w_hh, p_whhT, G4, HDIM);
    // 2) embedding gather -> bf16 concat-K triple
    gather_hl_kernel<<<(SQ*BQ*EDIM + 255)/256, 256>>>(questions, emb);
    // 3) w_ih -> bf16 triple
    convert_wih_kernel<<<(G4*EDIM + 255)/256, 256>>>(w_ih);
    // 4) Xg = Xe @ w_ih^T + b_ih + b_hh via HMMA concat-K (5120 x 1024, K'=384)
    gemm_mma_splitk<<<dim3(G4/128, (SQ*BQ)/128, 1), 256, mma_smem>>>(
        p_Xehl, nullptr, p_Bwih, nullptr, nullptr, G4, 384, 384, 1, b_ih, b_hh, p_Xg);
    // 5) full LSTM recurrence in ONE persistent kernel (final h -> d_hbuf[1])
    lstm_fused_kernel<<<dim3(16, 8), 128, lstm_smem>>>();
    // 6) weight transconversions for the big GEMMs
    transconv_kernel<<<dim3(FLAT/32, 512/32), 256>>>(lw1, p_Bthi, p_Btlo, FLAT, 512);
    transconv_kernel<<<dim3(G4/32, H16/32), 256>>>(hw2, p_Bt2hi, p_Bt2lo, G4, H16);
    transconv_kernel<<<dim3(H16/32, (TOT+31)/32), 256>>>(hw3, p_Bt3hi, p_Bt3lo, H16, TOT);
    // 7) hw1 fp32 (K=256 too small for HMMA payoff) + hi/lo convert
    gemm_nn_kernel<1, false><<<dim3(G4/64, BQ/64), 256>>>(
        p_hbuf + BQ*HDIM, hw1, hb1, nullptr, p_h1, BQ, G4, HDIM);
    convert_hilo_kernel<<<BQ*G4/1024, 256>>>(p_h1, p_h1hi, p_h1lo);
    // 8) hw2 (256 x 4096, K=1024): 4-way K-split, 3 phases fused in-kernel
    gemm_mma_splitk<<<dim3(H16/128, BQ/128, 4), 256, mma_smem>>>(
        p_h1hi, p_h1lo, p_Bt2hi, p_Bt2lo, p_gpart, H16, G4, G4/4, 3,
        nullptr, nullptr, nullptr);
    reduce_hw2_kernel<<<BQ*H16/256, 256>>>(hb2);
    // 9) hw3 (256 x 2768, K=4096): 8-way K-split, 3 phases fused
    gemm_mma_splitk<<<dim3((TOT+127)/128, BQ/128, 8), 256, mma_smem>>>(
        p_h2hi, p_h2lo, p_Bt3hi, p_Bt3lo, p_gpart, TOT, H16, H16/8, 3,
        nullptr, nullptr, nullptr);
    reduce_hw3_kernel<<<BQ*TOT/256, 256>>>(hb3);
    // 10) per-sample convs (conv2 emits fc1's bf16 hi/lo A directly)
    conv1_kernel<<<BQ, 256, conv1_smem>>>(images);
    conv2_kernel<<<dim3(4, BQ), 256, conv2_smem>>>();
    // 11) fc1 (256 x 512, K=65536): 32-way K-split, 3 phases fused
    gemm_mma_splitk<<<dim3(512/128, BQ/128, 32), 256, mma_smem>>>(
        p_Ahi, p_Alo, p_Bthi, p_Btlo, p_gpart, 512, FLAT, FLAT/32, 3,
        nullptr, nullptr, nullptr);
    fc1_reduce_kernel<<<(BQ*512 + 255)/256, 256>>>(lb1);
    // 12) fused fc2 (relu) + fc3
    fc23_kernel<<<BQ, 64>>>(lw2, lb2, lw3, lb3, out);
}

// round 14
// speedup vs baseline: 1.0285x; 1.0285x over previous
#include <cuda_runtime.h>
#include <cuda_bf16.h>
#include <math.h>
#include <stdint.h>

// ---------------- problem constants ----------------
#define BQ    256        // batch
#define SQ    20         // seq len
#define EDIM  128        // embedding dim
#define HDIM  256        // lstm hidden
#define G4    1024       // 4*H
#define H16   4096       // 16*H
#define TOT   2768       // hypernet output width
#define IMG   64
#define FLAT  65536      // 16*64*64
#define SLOPE (1.0f/5.5f)

// ---------------- device scratch (static, no allocs) ----------------
__device__ float d_Xg[SQ*BQ*G4];
__device__ float d_whhT[HDIM*G4];
__device__ float d_hbuf[2][BQ*HDIM];
__device__ float d_h1[BQ*G4];
__device__ float d_allw[BQ*TOT];
__device__ float d_conv1o[BQ*16*IMG*IMG];
// bf16 operands
__device__ __nv_bfloat16 d_Xehl[SQ*BQ*384];     // [Ah|Al|Ah] for Xg gemm
__device__ __nv_bfloat16 d_Bwih[G4*384];        // [Bh|Bh|Bl] of w_ih
__device__ __nv_bfloat16 d_Ahi[BQ*FLAT];        // fc1 A hi (written by conv2)
__device__ __nv_bfloat16 d_Alo[BQ*FLAT];
__device__ __nv_bfloat16 d_Bthi[512*FLAT];      // lw1^T  (512 x 65536)
__device__ __nv_bfloat16 d_Btlo[512*FLAT];
__device__ __nv_bfloat16 d_Bt2hi[H16*G4];       // hw2^T  (4096 x 1024)
__device__ __nv_bfloat16 d_Bt2lo[H16*G4];
__device__ __nv_bfloat16 d_Bt3hi[TOT*H16];      // hw3^T  (2768 x 4096)
__device__ __nv_bfloat16 d_Bt3lo[TOT*H16];
__device__ __nv_bfloat16 d_h1hi[BQ*G4];
__device__ __nv_bfloat16 d_h1lo[BQ*G4];
__device__ __nv_bfloat16 d_h2hi[BQ*H16];
__device__ __nv_bfloat16 d_h2lo[BQ*H16];
// shared split-K partial buffer (sequentially reused by hw2, hw3, fc1)
#define GPART_ELEMS (8*256*4096)                // 33.5 MB
__device__ float d_gpart[GPART_ELEMS];
__device__ float d_fc1[BQ*512];
// persistent-LSTM grid barrier state
__device__ unsigned d_barc = 0;
__device__ unsigned d_barg = 0;

__device__ __forceinline__ float sigmoidf_(float x) { return 1.0f / (1.0f + expf(-x)); }

__device__ __forceinline__ uint32_t smem_u32(const void* p) {
    uint32_t a;
    asm("{ .reg .u64 t; cvta.to.shared.u64 t, %1; cvt.u32.u64 %0, t; }" : "=r"(a) : "l"(p));
    return a;
}

// ---------------- input conversion kernels ----------------
__global__ void gather_hl_kernel(const int* __restrict__ q, const float* __restrict__ emb) {
    int idx = blockIdx.x * 256 + threadIdx.x;
    if (idx < SQ*BQ*EDIM) {
        int e = idx & 127, m = idx >> 7;
        int tt = m / BQ, bb = m % BQ;
        float v = emb[(size_t)q[bb*SQ + tt] * EDIM + e];
        __nv_bfloat16 h = __float2bfloat16(v);
        __nv_bfloat16 l = __float2bfloat16(v - __bfloat162float(h));
        d_Xehl[(size_t)m*384 + e]       = h;
        d_Xehl[(size_t)m*384 + 128 + e] = l;
        d_Xehl[(size_t)m*384 + 256 + e] = h;
    }
}

__global__ void convert_wih_kernel(const float* __restrict__ w_ih) {
    int i = blockIdx.x * 256 + threadIdx.x;    // 131072
    int n = i >> 7, k = i & 127;
    float v = w_ih[i];
    __nv_bfloat16 h = __float2bfloat16(v);
    __nv_bfloat16 l = __float2bfloat16(v - __bfloat162float(h));
    d_Bwih[(size_t)n*384 + k]       = h;
    d_Bwih[(size_t)n*384 + 128 + k] = h;
    d_Bwih[(size_t)n*384 + 256 + k] = l;
}

__global__ void transpose_kernel(const float* __restrict__ src, float* __restrict__ dst,
                                 int R, int C) {
    int i = blockIdx.x * 256 + threadIdx.x;
    if (i < R*C) { int r = i / C, c = i % C; dst[(size_t)c*R + r] = src[i]; }
}

__global__ void convert_hilo_kernel(const float* __restrict__ src,
                                    __nv_bfloat16* __restrict__ hi,
                                    __nv_bfloat16* __restrict__ lo) {
    size_t i = ((size_t)blockIdx.x * 256 + threadIdx.x) * 4;
    float4 v = *(const float4*)(src + i);
    float vv[4] = {v.x, v.y, v.z, v.w};
    __nv_bfloat16 h[4], l[4];
#pragma unroll
    for (int j = 0; j < 4; j++) {
        h[j] = __float2bfloat16(vv[j]);
        l[j] = __float2bfloat16(vv[j] - __bfloat162float(h[j]));
    }
    __nv_bfloat162* ph = (__nv_bfloat162*)(hi + i);
    __nv_bfloat162* pl = (__nv_bfloat162*)(lo + i);
    ph[0] = __nv_bfloat162{h[0], h[1]}; ph[1] = __nv_bfloat162{h[2], h[3]};
    pl[0] = __nv_bfloat162{l[0], l[1]}; pl[1] = __nv_bfloat162{l[2], l[3]};
}

__global__ void transconv_kernel(const float* __restrict__ src,
                                 __nv_bfloat16* __restrict__ dsthi,
                                 __nv_bfloat16* __restrict__ dstlo, int K, int N) {
    __shared__ float t[32][33];
    const int k0 = blockIdx.x * 32;
    const int n0 = blockIdx.y * 32;
    const int tx = threadIdx.x & 31, ty = threadIdx.x >> 5;
    for (int r = ty; r < 32; r += 8) {
        int n = n0 + tx;
        t[r][tx] = (n < N) ? src[(size_t)(k0 + r) * N + n] : 0.0f;
    }
    __syncthreads();
    for (int r = ty; r < 32; r += 8) {
        if (n0 + r < N) {
            float x = t[tx][r];
            __nv_bfloat16 h = __float2bfloat16(x);
            __nv_bfloat16 l = __float2bfloat16(x - __bfloat162float(h));
            size_t o = (size_t)(n0 + r) * K + k0 + tx;
            dsthi[o] = h;
            dstlo[o] = l;
        }
    }
}

// ---------------- generic fp32 GEMM (used for hw1 only) ----------------
template<int ACT, bool BIAS2>
__global__ void gemm_nn_kernel(const float* __restrict__ A, const float* __restrict__ B,
                               const float* __restrict__ bias, const float* __restrict__ bias2,
                               float* __restrict__ C, int M, int N, int K) {
    __shared__ float As[16][68];
    __shared__ float Bs[16][64];
    const int tid = threadIdx.x;
    const int m0 = blockIdx.y * 64;
    const int n0 = blockIdx.x * 64;
    const int ty = tid >> 4, tx = tid & 15;
    const int ar = tid >> 2, ac = (tid & 3) << 2;
    const int br = tid >> 4, bc = (tid & 15) << 2;

    float acc[4][4];
#pragma unroll
    for (int i = 0; i < 4; i++)
#pragma unroll
        for (int j = 0; j < 4; j++) acc[i][j] = 0.0f;

    for (int k0 = 0; k0 < K; k0 += 16) {
        float4 av = *(const float4*)(A + (size_t)(m0 + ar) * K + k0 + ac);
        As[ac+0][ar] = av.x; As[ac+1][ar] = av.y; As[ac+2][ar] = av.z; As[ac+3][ar] = av.w;
        float4 bv = *(const float4*)(B + (size_t)(k0 + br) * N + n0 + bc);
        *(float4*)&Bs[br][bc] = bv;
        __syncthreads();
#pragma unroll
        for (int k = 0; k < 16; k++) {
            float a0 = As[k][ty*4+0], a1 = As[k][ty*4+1];
            float a2 = As[k][ty*4+2], a3 = As[k][ty*4+3];
            float4 b4 = *(const float4*)&Bs[k][tx*4];
            acc[0][0] += a0*b4.x; acc[0][1] += a0*b4.y; acc[0][2] += a0*b4.z; acc[0][3] += a0*b4.w;
            acc[1][0] += a1*b4.x; acc[1][1] += a1*b4.y; acc[1][2] += a1*b4.z; acc[1][3] += a1*b4.w;
            acc[2][0] += a2*b4.x; acc[2][1] += a2*b4.y; acc[2][2] += a2*b4.z; acc[2][3] += a2*b4.w;
            acc[3][0] += a3*b4.x; acc[3][1] += a3*b4.y; acc[3][2] += a3*b4.z; acc[3][3] += a3*b4.w;
        }
        __syncthreads();
    }

#pragma unroll
    for (int i = 0; i < 4; i++) {
        int row = m0 + ty*4 + i;
#pragma unroll
        for (int j = 0; j < 4; j++) {
            int col = n0 + tx*4 + j;
            float v = acc[i][j] + bias[col];
            if (BIAS2) v += bias2[col];
            if (ACT == 1) v = (v > 0.0f) ? v : v * SLOPE;
            else if (ACT == 2) v = fmaxf(v, 0.0f);
            C[(size_t)row * N + col] = v;
        }
    }
}

// ---------------- unified HMMA GEMM ----------------
// XOR-swizzled smem layout (conflict-free ldmatrix), 3-stage cp.async pipeline,
// single __syncthreads per iteration, fused hi/lo phases (accumulate in regs).
//   tile = 128 rows x 64 bf16, element (r, kchunk 0..7) at byte r*128 + ((kchunk^(r&7))<<4)
#define TILE_E 8192   // 128*64 bf16 elements per tile (16 KB)
#define STAGE_E (2*TILE_E)
__device__ __forceinline__ void g2s_stage(
    const __nv_bfloat16* __restrict__ Aptr, const __nv_bfloat16* __restrict__ Bptr,
    __nv_bfloat16* sA, __nv_bfloat16* sB,
    int tid, int m0, int n0, int N, size_t K, size_t k0) {
#pragma unroll
    for (int c8 = 0; c8 < 8; c8++) {
        int c = tid + (c8 << 8);
        int r = (c & 1023) >> 3, kch = c & 7;
        int soff = r * 64 + ((kch ^ (r & 7)) << 3);
        if (c < 1024) {
            const void* g = Aptr + (size_t)(m0 + r) * K + k0 + kch * 8;
            uint32_t s = smem_u32(sA + soff);
            asm volatile("cp.async.cg.shared.global [%0], [%1], 16;" :: "r"(s), "l"(g));
        } else {
            int valid = (n0 + r) < N;
            const void* g = Bptr + (valid ? ((size_t)(n0 + r) * K + k0 + kch * 8) : 0);
            uint32_t s = smem_u32(sB + soff);
            int sz = valid ? 16 : 0;
            asm volatile("cp.async.cg.shared.global [%0], [%1], 16, %2;" :: "r"(s), "l"(g), "r"(sz));
        }
    }
}

__global__ __launch_bounds__(256, 2) void gemm_mma_splitk(
    const __nv_bfloat16* __restrict__ Ahi, const __nv_bfloat16* __restrict__ Alo,
    const __nv_bfloat16* __restrict__ Bthi, const __nv_bfloat16* __restrict__ Btlo,
    float* __restrict__ Cpart, int N, int K, int kchunk, int nphase,
    const float* __restrict__ bias, const float* __restrict__ bias2,
    float* __restrict__ Cout) {
    extern __shared__ __nv_bfloat16 sm[];

    const int tid  = threadIdx.x;
    const int warp = tid >> 5, lane = tid & 31;
    const int n0 = blockIdx.x * 128;
    const int m0 = blockIdx.y * 128;
    const int M  = gridDim.y * 128;
    const int z  = blockIdx.z;
    const size_t kbase = (size_t)z * kchunk;
    const int iters = kchunk >> 6;
    const int total = nphase * iters;

    const __nv_bfloat16* Ap[3] = {Ahi, Alo, Ahi};
    const __nv_bfloat16* Bp[3] = {Bthi, Bthi, Btlo};

    const int wm = warp >> 2;
    const int wn = warp & 3;
    const int g  = lane >> 2, tig = lane & 3;

    float acc[4][4][4];
#pragma unroll
    for (int mt = 0; mt < 4; mt++)
#pragma unroll
        for (int nt = 0; nt < 4; nt++)
#pragma unroll
            for (int e = 0; e < 4; e++) acc[mt][nt][e] = 0.0f;

    // ldmatrix lane->(row, kchunk-within-pair) mapping
    const int a_row = lane & 15;            // + wm*64 + mt*16
    const int a_kc  = lane >> 4;            // 0/1 -> kchunk = ks*2 + a_kc
    const int b_row = (lane >> 4) * 8 + (lane & 7);  // + wn*32 + np*16
    const int b_kc  = (lane >> 3) & 1;

    // prologue: stage 0, stage 1
    g2s_stage(Ap[0], Bp[0], sm, sm + TILE_E, tid, m0, n0, N, K, kbase);
    asm volatile("cp.async.commit_group;" ::: "memory");
    if (total > 1) {
        int ph = 1 / iters, itk = 1 - ph * iters;
        g2s_stage(Ap[ph], Bp[ph], sm + STAGE_E, sm + STAGE_E + TILE_E,
                  tid, m0, n0, N, K, kbase + (size_t)itk * 64);
    }
    asm volatile("cp.async.commit_group;" ::: "memory");

    for (int j = 0; j < total; ++j) {
        asm volatile("cp.async.wait_group 1;" ::: "memory");
        __syncthreads();   // stage j%3 ready; all warps done consuming stage (j+2)%3 at iter j-1

        if (j + 2 < total) {
            int jn = j + 2;
            int ph = jn / iters, itk = jn - ph * iters;
            const int st2 = jn % 3;
            g2s_stage(Ap[ph], Bp[ph], sm + st2 * STAGE_E, sm + st2 * STAGE_E + TILE_E,
                      tid, m0, n0, N, K, kbase + (size_t)itk * 64);
        }
        asm volatile("cp.async.commit_group;" ::: "memory");

        const uint32_t sAb = smem_u32(sm) + (j % 3) * (STAGE_E * 2);
        const uint32_t sBb = sAb + TILE_E * 2;

#pragma unroll
        for (int ks = 0; ks < 4; ks++) {
            uint32_t a[4][4];
#pragma unroll
            for (int mt = 0; mt < 4; mt++) {
                int r = wm*64 + mt*16 + a_row;
                int kch = ks*2 + a_kc;
                uint32_t addr = sAb + r * 128 + (((kch ^ (r & 7))) << 4);
                asm volatile("ldmatrix.sync.aligned.m8n8.x4.shared.b16 {%0,%1,%2,%3}, [%4];"
                    : "=r"(a[mt][0]), "=r"(a[mt][1]), "=r"(a[mt][2]), "=r"(a[mt][3])
                    : "r"(addr));
            }
            uint32_t b[4][2];
#pragma unroll
            for (int np = 0; np < 2; np++) {
                int r = wn*32 + np*16 + b_row;
                int kch = ks*2 + b_kc;
                uint32_t addr = sBb + r * 128 + (((kch ^ (r & 7))) << 4);
                uint32_t r0, r1, r2, r3;
                asm volatile("ldmatrix.sync.aligned.m8n8.x4.shared.b16 {%0,%1,%2,%3}, [%4];"
                    : "=r"(r0), "=r"(r1), "=r"(r2), "=r"(r3) : "r"(addr));
                b[np*2+0][0] = r0; b[np*2+0][1] = r1;
                b[np*2+1][0] = r2; b[np*2+1][1] = r3;
            }
#pragma unroll
            for (int mt = 0; mt < 4; mt++)
#pragma unroll
                for (int nt = 0; nt < 4; nt++) {
                    asm volatile(
                        "mma.sync.aligned.m16n8k16.row.col.f32.bf16.bf16.f32 "
                        "{%0,%1,%2,%3}, {%4,%5,%6,%7}, {%8,%9}, {%0,%1,%2,%3};"
                        : "+f"(acc[mt][nt][0]), "+f"(acc[mt][nt][1]),
                          "+f"(acc[mt][nt][2]), "+f"(acc[mt][nt][3])
                        : "r"(a[mt][0]), "r"(a[mt][1]), "r"(a[mt][2]), "r"(a[mt][3]),
                          "r"(b[nt][0]), "r"(b[nt][1]));
                }
        }
        __syncthreads();   // done consuming stage j%3 (refilled at iter j+1 as stage (j+3)%3... = j%3)
    }

    if (Cpart) {
        float* outz = Cpart + (size_t)z * M * N;
#pragma unroll
        for (int mt = 0; mt < 4; mt++)
#pragma unroll
            for (int nt = 0; nt < 4; nt++) {
                int row0 = m0 + wm*64 + mt*16 + g;
                int col  = n0 + wn*32 + nt*8 + tig*2;
                if (col < N) {
                    *(float2*)(outz + (size_t)row0 * N + col)
                        = make_float2(acc[mt][nt][0], acc[mt][nt][1]);
                    *(float2*)(outz + (size_t)(row0 + 8) * N + col)
                        = make_float2(acc[mt][nt][2], acc[mt][nt][3]);
                }
            }
    } else {
#pragma unroll
        for (int mt = 0; mt < 4; mt++)
#pragma unroll
            for (int nt = 0; nt < 4; nt++) {
                int row0 = m0 + wm*64 + mt*16 + g;
                int col  = n0 + wn*32 + nt*8 + tig*2;
                if (col < N) {
                    float b0v = bias[col]   + (bias2 ? bias2[col]   : 0.0f);
                    float b1v = bias[col+1] + (bias2 ? bias2[col+1] : 0.0f);
                    *(float2*)(Cout + (size_t)row0 * N + col)
                        = make_float2(acc[mt][nt][0] + b0v, acc[mt][nt][1] + b1v);
                    *(float2*)(Cout + (size_t)(row0 + 8) * N + col)
                        = make_float2(acc[mt][nt][2] + b0v, acc[mt][nt][3] + b1v);
                }
            }
    }
}

// ---------------- split-K reduce kernels ----------------
__global__ void reduce_hw2_kernel(const float* __restrict__ hb2) {
    int i = blockIdx.x * 256 + threadIdx.x;
    float s = hb2[i & (H16-1)];
#pragma unroll
    for (int zz = 0; zz < 4; zz++) s += d_gpart[(size_t)zz * (BQ*H16) + i];
    s = (s > 0.0f) ? s : s * SLOPE;
    __nv_bfloat16 h = __float2bfloat16(s);
    d_h2hi[i] = h;
    d_h2lo[i] = __float2bfloat16(s - __bfloat162float(h));
}

__global__ void reduce_hw3_kernel(const float* __restrict__ hb3) {
    int i = blockIdx.x * 256 + threadIdx.x;
    int col = i % TOT;
    float s = hb3[col];
#pragma unroll
    for (int zz = 0; zz < 8; zz++) s += d_gpart[(size_t)zz * (BQ*TOT) + i];
    d_allw[i] = s;
}

__global__ void fc1_reduce_kernel(const float* __restrict__ lb1) {
    int i = blockIdx.x * 256 + threadIdx.x;
    float s = lb1[i & 511];
#pragma unroll
    for (int zz = 0; zz < 32; zz++) s += d_gpart[(size_t)zz * (BQ*512) + i];
    d_fc1[i] = s;
}

// ---------------- persistent fused LSTM (unchanged) ----------------
__global__ __launch_bounds__(128) void lstm_fused_kernel() {
    extern __shared__ float lsm[];
    float* ws = lsm;               // [256][64]
    float* hs = lsm + 256*64;      // [256][33]

    const int tid = threadIdx.x;
    const int u0 = blockIdx.x * 16;
    const int b0 = blockIdx.y * 32;
    const int tx = tid & 15;
    const int ty = tid >> 4;

    for (int e = tid; e < 16384; e += 128) {
        int kk = e >> 6, c = e & 63;
        int gg = c >> 4, uu = c & 15;
        ws[e] = d_whhT[(size_t)kk * G4 + gg * HDIM + u0 + uu];
    }

    float creg[4] = {0.f, 0.f, 0.f, 0.f};

    for (int t = 0; t < SQ; t++) {
        float acc[4][4];
#pragma unroll
        for (int bi = 0; bi < 4; bi++)
#pragma unroll
            for (int gg = 0; gg < 4; gg++) acc[bi][gg] = 0.0f;

        if (t > 0) {
            const float* hsrc = d_hbuf[(t-1) & 1];
            for (int e = tid; e < 8192; e += 128) {
                int bb = e >> 8, kk = e & 255;
                hs[kk*33 + bb] = __ldcg(&hsrc[(b0 + bb) * HDIM + kk]);
            }
            __syncthreads();
#pragma unroll 4
            for (int k = 0; k < 256; k++) {
                float w0 = ws[k*64 +      tx];
                float w1 = ws[k*64 + 16 + tx];
                float w2 = ws[k*64 + 32 + tx];
                float w3 = ws[k*64 + 48 + tx];
#pragma unroll
                for (int bi = 0; bi < 4; bi++) {
                    float h = hs[k*33 + ty*4 + bi];
                    acc[bi][0] += h * w0; acc[bi][1] += h * w1;
                    acc[bi][2] += h * w2; acc[bi][3] += h * w3;
                }
            }
        }

        float* hdst = d_hbuf[t & 1];
#pragma unroll
        for (int bi = 0; bi < 4; bi++) {
            int b = b0 + ty*4 + bi;
            const float* xg = d_Xg + ((size_t)t * BQ + b) * G4 + u0 + tx;
            float iv = sigmoidf_(acc[bi][0] + xg[0]);
            float fv = sigmoidf_(acc[bi][1] + xg[HDIM]);
            float gv = tanhf    (acc[bi][2] + xg[2*HDIM]);
            float ov = sigmoidf_(acc[bi][3] + xg[3*HDIM]);
            float c = fv * creg[bi] + iv * gv;
            creg[bi] = c;
            hdst[b * HDIM + u0 + tx] = ov * tanhf(c);
        }

        if (t < SQ - 1) {
            __syncthreads();
            __threadfence();
            if (tid == 0) {
                unsigned gen = atomicAdd(&d_barg, 0u);
                if (atomicAdd(&d_barc, 1u) == 127u) {
                    atomicExch(&d_barc, 0u);
                    __threadfence();
                    atomicExch(&d_barg, gen + 1u);
                } else {
                    while (atomicAdd(&d_barg, 0u) == gen) __nanosleep(64);
                }
                __threadfence();
            }
            __syncthreads();
        }
    }
}

// ---------------- conv1 (unchanged) ----------------
__global__ void conv1_kernel(const float* __restrict__ images) {
    extern __shared__ float smf[];
    float* sin = smf;
    float* sw  = smf + 3*4096;
    float* sb  = sw + 432;
    const int b = blockIdx.x;
    const int tid = threadIdx.x;

    const float* ip = images + (size_t)b * 3 * 4096;
    for (int i = tid; i < 3*4096; i += 256) sin[i] = ip[i];
    const float* wp = d_allw + (size_t)b * TOT;
    for (int i = tid; i < 448; i += 256) {
        if (i < 432) sw[i] = wp[i]; else sb[i-432] = wp[i];
    }
    __syncthreads();

    for (int task = tid; task < 16*64*4; task += 256) {
        int oc = task >> 8;
        int y  = (task >> 2) & 63;
        int x0 = (task & 3) << 4;
        float accs[16];
#pragma unroll
        for (int i = 0; i < 16; i++) accs[i] = 0.0f;

        for (int ic = 0; ic < 3; ic++) {
#pragma unroll
            for (int ky = 0; ky < 3; ky++) {
                int yy = y + ky - 1;
                if (yy < 0 || yy >= 64) continue;
                const float* row = sin + ic*4096 + yy*64;
                const float* w3  = sw + ((oc*3 + ic)*3 + ky)*3;
                float w0 = w3[0], w1 = w3[1], w2 = w3[2];
                float vals[18];
#pragma unroll
                for (int i = 0; i < 18; i++) {
                    int x = x0 + i - 1;
                    vals[i] = (x >= 0 && x < 64) ? row[x] : 0.0f;
                }
#pragma unroll
                for (int i = 0; i < 16; i++)
                    accs[i] += w0*vals[i] + w1*vals[i+1] + w2*vals[i+2];
            }
        }
        float bv = sb[oc];
        float* op = d_conv1o + (((size_t)b*16 + oc)*64 + y)*64 + x0;
#pragma unroll
        for (int i = 0; i < 16; i++) op[i] = accs[i] + bv;
    }
}

// ---------------- conv2: writes bf16 hi/lo directly (unchanged) ----------------
__global__ void conv2_kernel() {
    extern __shared__ float smf[];
    float* sin = smf;
    float* sw  = smf + 16*18*64;
    float* sb  = sw + 2304;
    const int b  = blockIdx.y;
    const int y0 = blockIdx.x * 16;
    const int tid = threadIdx.x;

    const float* ip = d_conv1o + (size_t)b * 16 * 4096;
    for (int i = tid; i < 16*18*64; i += 256) {
        int ic = i / (18*64);
        int r  = (i / 64) % 18;
        int x  = i & 63;
        int yy = y0 + r - 1;
        sin[i] = (yy >= 0 && yy < 64) ? ip[ic*4096 + yy*64 + x] : 0.0f;
    }
    const float* wp = d_allw + (size_t)b * TOT + 448;
    for (int i = tid; i < 2320; i += 256) {
        if (i < 2304) sw[i] = wp[i]; else sb[i-2304] = wp[i];
    }
    __syncthreads();

    const int pos = tid & 63;
    const int ocg = tid >> 6;
    const int y  = pos >> 2;
    const int x0 = (pos & 3) << 4;

    float acc[4][16];
#pragma unroll
    for (int o = 0; o < 4; o++)
#pragma unroll
        for (int i = 0; i < 16; i++) acc[o][i] = 0.0f;

    for (int ic = 0; ic < 16; ic++) {
#pragma unroll
        for (int ky = 0; ky < 3; ky++) {
            const float* row = sin + (ic*18 + y + ky) * 64;
            float w[4][3];
#pragma unroll
            for (int o = 0; o < 4; o++)
#pragma unroll
                for (int kx = 0; kx < 3; kx++)
                    w[o][kx] = sw[(((ocg*4 + o)*16 + ic)*3 + ky)*3 + kx];
            float vals[18];
#pragma unroll
            for (int i = 0; i < 18; i++) {
                int x = x0 + i - 1;
                vals[i] = (x >= 0 && x < 64) ? row[x] : 0.0f;
            }
#pragma unroll
            for (int o = 0; o < 4; o++)
#pragma unroll
                for (int i = 0; i < 16; i++)
                    acc[o][i] += w[o][0]*vals[i] + w[o][1]*vals[i+1] + w[o][2]*vals[i+2];
        }
    }
#pragma unroll
    for (int o = 0; o < 4; o++) {
        int oc = ocg*4 + o;
        float bv = sb[oc];
        size_t base = (((size_t)b*16 + oc)*64 + (y0 + y))*64 + x0;
#pragma unroll
        for (int i = 0; i < 16; i++) {
            float v = acc[o][i] + bv;
            __nv_bfloat16 h = __float2bfloat16(v);
            d_Ahi[base + i] = h;
            d_Alo[base + i] = __float2bfloat16(v - __bfloat162float(h));
        }
    }
}

// ---------------- fused fc2 + fc3 (unchanged) ----------------
__global__ void fc23_kernel(const float* __restrict__ lw2, const float* __restrict__ lb2,
                            const float* __restrict__ lw3, const float* __restrict__ lb3,
                            float* __restrict__ out) {
    const int b = blockIdx.x;
    const int j = threadIdx.x;
    const float* a = d_fc1 + (size_t)b * 512;
    float acc = lb2[j];
#pragma unroll 4
    for (int k = 0; k < 512; k++)
        acc += fmaxf(a[k], 0.0f) * lw2[(size_t)k*64 + j];
    acc = fmaxf(acc, 0.0f);
    __shared__ float h[64];
    h[j] = acc;
    __syncthreads();
    if (j < 2) {
        float s = lb3[j];
#pragma unroll
        for (int q = 0; q < 64; q++) s += h[q] * lw3[q*2 + j];
        out[b*2 + j] = s;
    }
}

// ---------------- launch ----------------
extern "C" void kernel_launch(void* const* d_in, const int* in_sizes, int n_in,
                              void* d_out, int out_size) {
    const int*   questions = (const int*)  d_in[0];
    const float* images    = (const float*)d_in[1];
    const float* emb       = (const float*)d_in[2];
    const float* w_ih      = (const float*)d_in[3];
    const float* w_hh      = (const float*)d_in[4];
    const float* b_ih      = (const float*)d_in[5];
    const float* b_hh      = (const float*)d_in[6];
    const float* hw1       = (const float*)d_in[7];
    const float* hb1       = (const float*)d_in[8];
    const float* hw2       = (const float*)d_in[9];
    const float* hb2       = (const float*)d_in[10];
    const float* hw3       = (const float*)d_in[11];
    const float* hb3       = (const float*)d_in[12];
    const float* lw1       = (const float*)d_in[13];
    const float* lb1       = (const float*)d_in[14];
    const float* lw2       = (const float*)d_in[15];
    const float* lb2       = (const float*)d_in[16];
    const float* lw3       = (const float*)d_in[17];
    const float* lb3       = (const float*)d_in[18];
    float* out = (float*)d_out;

    // __device__ symbols are NOT valid device pointers in host code: fetch real addresses.
    float *p_Xg, *p_whhT, *p_hbuf, *p_h1, *p_gpart;
    __nv_bfloat16 *p_Xehl, *p_Bwih, *p_Ahi, *p_Alo, *p_Bthi, *p_Btlo,
                  *p_Bt2hi, *p_Bt2lo, *p_Bt3hi, *p_Bt3lo,
                  *p_h1hi, *p_h1lo, *p_h2hi, *p_h2lo;
    cudaGetSymbolAddress((void**)&p_Xg,    d_Xg);
    cudaGetSymbolAddress((void**)&p_whhT,  d_whhT);
    cudaGetSymbolAddress((void**)&p_hbuf,  d_hbuf);
    cudaGetSymbolAddress((void**)&p_h1,    d_h1);
    cudaGetSymbolAddress((void**)&p_gpart, d_gpart);
    cudaGetSymbolAddress((void**)&p_Xehl,  d_Xehl);
    cudaGetSymbolAddress((void**)&p_Bwih,  d_Bwih);
    cudaGetSymbolAddress((void**)&p_Ahi,   d_Ahi);
    cudaGetSymbolAddress((void**)&p_Alo,   d_Alo);
    cudaGetSymbolAddress((void**)&p_Bthi,  d_Bthi);
    cudaGetSymbolAddress((void**)&p_Btlo,  d_Btlo);
    cudaGetSymbolAddress((void**)&p_Bt2hi, d_Bt2hi);
    cudaGetSymbolAddress((void**)&p_Bt2lo, d_Bt2lo);
    cudaGetSymbolAddress((void**)&p_Bt3hi, d_Bt3hi);
    cudaGetSymbolAddress((void**)&p_Bt3lo, d_Bt3lo);
    cudaGetSymbolAddress((void**)&p_h1hi,  d_h1hi);
    cudaGetSymbolAddress((void**)&p_h1lo,  d_h1lo);
    cudaGetSymbolAddress((void**)&p_h2hi,  d_h2hi);
    cudaGetSymbolAddress((void**)&p_h2lo,  d_h2lo);

    const int conv1_smem = (3*4096 + 448) * 4;
    const int conv2_smem = (16*18*64 + 2320) * 4;
    const int mma_smem   = 3 * STAGE_E * 2;          // 98304 B (3 stages, 2 CTAs/SM)
    const int lstm_smem  = (16384 + 256*33) * 4;     // 99328 B
    cudaFuncSetAttribute(conv1_kernel, cudaFuncAttributeMaxDynamicSharedMemorySize, conv1_smem);
    cudaFuncSetAttribute(conv2_kernel, cudaFuncAttributeMaxDynamicSharedMemorySize, conv2_smem);
    cudaFuncSetAttribute(gemm_mma_splitk, cudaFuncAttributeMaxDynamicSharedMemorySize, mma_smem);
    cudaFuncSetAttribute(lstm_fused_kernel, cudaFuncAttributeMaxDynamicSharedMemorySize, lstm_smem);

    // 1) transpose w_hh (fp32, for LSTM smem)
    transpose_kernel<<<(G4*HDIM + 255)/256, 256>>>(w_hh, p_whhT, G4, HDIM);
    // 2) embedding gather -> bf16 concat-K triple
    gather_hl_kernel<<<(SQ*BQ*EDIM + 255)/256, 256>>>(questions, emb);
    // 3) w_ih -> bf16 triple
    convert_wih_kernel<<<(G4*EDIM + 255)/256, 256>>>(w_ih);
    // 4) Xg = Xe @ w_ih^T + b_ih + b_hh via HMMA concat-K (5120 x 1024, K'=384)
    gemm_mma_splitk<<<dim3(G4/128, (SQ*BQ)/128, 1), 256, mma_smem>>>(
        p_Xehl, nullptr, p_Bwih, nullptr, nullptr, G4, 384, 384, 1, b_ih, b_hh, p_Xg);
    // 5) full LSTM recurrence in ONE persistent kernel (final h -> d_hbuf[1])
    lstm_fused_kernel<<<dim3(16, 8), 128, lstm_smem>>>();
    // 6) weight transconversions for the big GEMMs
    transconv_kernel<<<dim3(FLAT/32, 512/32), 256>>>(lw1, p_Bthi, p_Btlo, FLAT, 512);
    transconv_kernel<<<dim3(G4/32, H16/32), 256>>>(hw2, p_Bt2hi, p_Bt2lo, G4, H16);
    transconv_kernel<<<dim3(H16/32, (TOT+31)/32), 256>>>(hw3, p_Bt3hi, p_Bt3lo, H16, TOT);
    // 7) hw1 fp32 (K=256 too small for HMMA payoff) + hi/lo convert
    gemm_nn_kernel<1, false><<<dim3(G4/64, BQ/64), 256>>>(
        p_hbuf + BQ*HDIM, hw1, hb1, nullptr, p_h1, BQ, G4, HDIM);
    convert_hilo_kernel<<<BQ*G4/1024, 256>>>(p_h1, p_h1hi, p_h1lo);
    // 8) hw2 (256 x 4096, K=1024): 4-way K-split, 3 phases fused in-kernel
    gemm_mma_splitk<<<dim3(H16/128, BQ/128, 4), 256, mma_smem>>>(
        p_h1hi, p_h1lo, p_Bt2hi, p_Bt2lo, p_gpart, H16, G4, G4/4, 3,
        nullptr, nullptr, nullptr);
    reduce_hw2_kernel<<<BQ*H16/256, 256>>>(hb2);
    // 9) hw3 (256 x 2768, K=4096): 8-way K-split, 3 phases fused
    gemm_mma_splitk<<<dim3((TOT+127)/128, BQ/128, 8), 256, mma_smem>>>(
        p_h2hi, p_h2lo, p_Bt3hi, p_Bt3lo, p_gpart, TOT, H16, H16/8, 3,
        nullptr, nullptr, nullptr);
    reduce_hw3_kernel<<<BQ*TOT/256, 256>>>(hb3);
    // 10) per-sample convs (conv2 emits fc1's bf16 hi/lo A directly)
    conv1_kernel<<<BQ, 256, conv1_smem>>>(images);
    conv2_kernel<<<dim3(4, BQ), 256, conv2_smem>>>();
    // 11) fc1 (256 x 512, K=65536): 32-way K-split, 3 phases fused
    gemm_mma_splitk<<<dim3(512/128, BQ/128, 32), 256, mma_smem>>>(
        p_Ahi, p_Alo, p_Bthi, p_Btlo, p_gpart, 512, FLAT, FLAT/32, 3,
        nullptr, nullptr, nullptr);
    fc1_reduce_kernel<<<(BQ*512 + 255)/256, 256>>>(lb1);
    // 12) fused fc2 (relu) + fc3
    fc23_kernel<<<BQ, 64>>>(lw2, lb2, lw3, lb3, out);
}

// round 16
// speedup vs baseline: 1.0509x; 1.0217x over previous
#include <cuda_runtime.h>
#include <cuda_bf16.h>
#include <math.h>
#include <stdint.h>

// ---------------- problem constants ----------------
#define BQ    256        // batch
#define SQ    20         // seq len
#define EDIM  128        // embedding dim
#define HDIM  256        // lstm hidden
#define G4    1024       // 4*H
#define H16   4096       // 16*H
#define TOT   2768       // hypernet output width
#define IMG   64
#define FLAT  65536      // 16*64*64
#define SLOPE (1.0f/5.5f)

// ---------------- device scratch (static, no allocs) ----------------
__device__ float d_Xg[SQ*BQ*G4];
__device__ float d_whhT[HDIM*G4];
__device__ float d_hbuf[2][BQ*HDIM];
__device__ float d_h1[BQ*G4];
__device__ float d_allw[BQ*TOT];
__device__ float d_conv1o[BQ*16*IMG*IMG];
// bf16 operands
__device__ __nv_bfloat16 d_Xehl[SQ*BQ*384];     // [Ah|Al|Ah] for Xg gemm
__device__ __nv_bfloat16 d_Bwih[G4*384];        // [Bh|Bh|Bl] of w_ih
__device__ __nv_bfloat16 d_Ahi[BQ*FLAT];        // fc1 A hi (written by conv2)
__device__ __nv_bfloat16 d_Alo[BQ*FLAT];
__device__ __nv_bfloat16 d_Bthi[512*FLAT];      // lw1^T  (512 x 65536)
__device__ __nv_bfloat16 d_Btlo[512*FLAT];
__device__ __nv_bfloat16 d_Bt2hi[H16*G4];       // hw2^T  (4096 x 1024)
__device__ __nv_bfloat16 d_Bt2lo[H16*G4];
__device__ __nv_bfloat16 d_Bt3hi[TOT*H16];      // hw3^T  (2768 x 4096)
__device__ __nv_bfloat16 d_Bt3lo[TOT*H16];
__device__ __nv_bfloat16 d_h1hi[BQ*G4];
__device__ __nv_bfloat16 d_h1lo[BQ*G4];
__device__ __nv_bfloat16 d_h2hi[BQ*H16];
__device__ __nv_bfloat16 d_h2lo[BQ*H16];
// shared split-K partial buffer (sequentially reused by hw2, hw3, fc1)
#define GPART_ELEMS (8*256*4096)                // 33.5 MB
__device__ float d_gpart[GPART_ELEMS];
__device__ float d_fc1[BQ*512];
// persistent-LSTM grid barrier state
__device__ unsigned d_barc = 0;
__device__ unsigned d_barg = 0;

__device__ __forceinline__ float sigmoidf_(float x) { return 1.0f / (1.0f + expf(-x)); }

__device__ __forceinline__ uint32_t smem_u32(const void* p) {
    uint32_t a;
    asm("{ .reg .u64 t; cvta.to.shared.u64 t, %1; cvt.u32.u64 %0, t; }" : "=r"(a) : "l"(p));
    return a;
}

// ---------------- packed fp32x2 math (FFMA2 — 2x fp32 rate, PTX-only) ----------------
__device__ __forceinline__ uint64_t pk2(float lo, float hi) {
    uint64_t r; asm("mov.b64 %0, {%1, %2};" : "=l"(r) : "f"(lo), "f"(hi)); return r;
}
__device__ __forceinline__ void upk2(float& lo, float& hi, uint64_t p) {
    asm("mov.b64 {%0, %1}, %2;" : "=f"(lo), "=f"(hi) : "l"(p));
}
#define FMA2(d, a, b) asm("fma.rn.f32x2 %0, %1, %2, %0;" : "+l"(d) : "l"(a), "l"(b))

// ---------------- input conversion kernels ----------------
__global__ void gather_hl_kernel(const int* __restrict__ q, const float* __restrict__ emb) {
    int idx = blockIdx.x * 256 + threadIdx.x;
    if (idx < SQ*BQ*EDIM) {
        int e = idx & 127, m = idx >> 7;
        int tt = m / BQ, bb = m % BQ;
        float v = emb[(size_t)q[bb*SQ + tt] * EDIM + e];
        __nv_bfloat16 h = __float2bfloat16(v);
        __nv_bfloat16 l = __float2bfloat16(v - __bfloat162float(h));
        d_Xehl[(size_t)m*384 + e]       = h;
        d_Xehl[(size_t)m*384 + 128 + e] = l;
        d_Xehl[(size_t)m*384 + 256 + e] = h;
    }
}

__global__ void convert_wih_kernel(const float* __restrict__ w_ih) {
    int i = blockIdx.x * 256 + threadIdx.x;    // 131072
    int n = i >> 7, k = i & 127;
    float v = w_ih[i];
    __nv_bfloat16 h = __float2bfloat16(v);
    __nv_bfloat16 l = __float2bfloat16(v - __bfloat162float(h));
    d_Bwih[(size_t)n*384 + k]       = h;
    d_Bwih[(size_t)n*384 + 128 + k] = h;
    d_Bwih[(size_t)n*384 + 256 + k] = l;
}

__global__ void transpose_kernel(const float* __restrict__ src, float* __restrict__ dst,
                                 int R, int C) {
    int i = blockIdx.x * 256 + threadIdx.x;
    if (i < R*C) { int r = i / C, c = i % C; dst[(size_t)c*R + r] = src[i]; }
}

__global__ void convert_hilo_kernel(const float* __restrict__ src,
                                    __nv_bfloat16* __restrict__ hi,
                                    __nv_bfloat16* __restrict__ lo) {
    size_t i = ((size_t)blockIdx.x * 256 + threadIdx.x) * 4;
    float4 v = *(const float4*)(src + i);
    float vv[4] = {v.x, v.y, v.z, v.w};
    __nv_bfloat16 h[4], l[4];
#pragma unroll
    for (int j = 0; j < 4; j++) {
        h[j] = __float2bfloat16(vv[j]);
        l[j] = __float2bfloat16(vv[j] - __bfloat162float(h[j]));
    }
    __nv_bfloat162* ph = (__nv_bfloat162*)(hi + i);
    __nv_bfloat162* pl = (__nv_bfloat162*)(lo + i);
    ph[0] = __nv_bfloat162{h[0], h[1]}; ph[1] = __nv_bfloat162{h[2], h[3]};
    pl[0] = __nv_bfloat162{l[0], l[1]}; pl[1] = __nv_bfloat162{l[2], l[3]};
}

__global__ void transconv_kernel(const float* __restrict__ src,
                                 __nv_bfloat16* __restrict__ dsthi,
                                 __nv_bfloat16* __restrict__ dstlo, int K, int N) {
    __shared__ float t[32][33];
    const int k0 = blockIdx.x * 32;
    const int n0 = blockIdx.y * 32;
    const int tx = threadIdx.x & 31, ty = threadIdx.x >> 5;
    for (int r = ty; r < 32; r += 8) {
        int n = n0 + tx;
        t[r][tx] = (n < N) ? src[(size_t)(k0 + r) * N + n] : 0.0f;
    }
    __syncthreads();
    for (int r = ty; r < 32; r += 8) {
        if (n0 + r < N) {
            float x = t[tx][r];
            __nv_bfloat16 h = __float2bfloat16(x);
            __nv_bfloat16 l = __float2bfloat16(x - __bfloat162float(h));
            size_t o = (size_t)(n0 + r) * K + k0 + tx;
            dsthi[o] = h;
            dstlo[o] = l;
        }
    }
}

// ---------------- generic fp32 GEMM (used for hw1 only) ----------------
template<int ACT, bool BIAS2>
__global__ void gemm_nn_kernel(const float* __restrict__ A, const float* __restrict__ B,
                               const float* __restrict__ bias, const float* __restrict__ bias2,
                               float* __restrict__ C, int M, int N, int K) {
    __shared__ float As[16][68];
    __shared__ float Bs[16][64];
    const int tid = threadIdx.x;
    const int m0 = blockIdx.y * 64;
    const int n0 = blockIdx.x * 64;
    const int ty = tid >> 4, tx = tid & 15;
    const int ar = tid >> 2, ac = (tid & 3) << 2;
    const int br = tid >> 4, bc = (tid & 15) << 2;

    float acc[4][4];
#pragma unroll
    for (int i = 0; i < 4; i++)
#pragma unroll
        for (int j = 0; j < 4; j++) acc[i][j] = 0.0f;

    for (int k0 = 0; k0 < K; k0 += 16) {
        float4 av = *(const float4*)(A + (size_t)(m0 + ar) * K + k0 + ac);
        As[ac+0][ar] = av.x; As[ac+1][ar] = av.y; As[ac+2][ar] = av.z; As[ac+3][ar] = av.w;
        float4 bv = *(const float4*)(B + (size_t)(k0 + br) * N + n0 + bc);
        *(float4*)&Bs[br][bc] = bv;
        __syncthreads();
#pragma unroll
        for (int k = 0; k < 16; k++) {
            float a0 = As[k][ty*4+0], a1 = As[k][ty*4+1];
            float a2 = As[k][ty*4+2], a3 = As[k][ty*4+3];
            float4 b4 = *(const float4*)&Bs[k][tx*4];
            acc[0][0] += a0*b4.x; acc[0][1] += a0*b4.y; acc[0][2] += a0*b4.z; acc[0][3] += a0*b4.w;
            acc[1][0] += a1*b4.x; acc[1][1] += a1*b4.y; acc[1][2] += a1*b4.z; acc[1][3] += a1*b4.w;
            acc[2][0] += a2*b4.x; acc[2][1] += a2*b4.y; acc[2][2] += a2*b4.z; acc[2][3] += a2*b4.w;
            acc[3][0] += a3*b4.x; acc[3][1] += a3*b4.y; acc[3][2] += a3*b4.z; acc[3][3] += a3*b4.w;
        }
        __syncthreads();
    }

#pragma unroll
    for (int i = 0; i < 4; i++) {
        int row = m0 + ty*4 + i;
#pragma unroll
        for (int j = 0; j < 4; j++) {
            int col = n0 + tx*4 + j;
            float v = acc[i][j] + bias[col];
            if (BIAS2) v += bias2[col];
            if (ACT == 1) v = (v > 0.0f) ? v : v * SLOPE;
            else if (ACT == 2) v = fmaxf(v, 0.0f);
            C[(size_t)row * N + col] = v;
        }
    }
}

// ---------------- unified HMMA GEMM (unchanged from R14) ----------------
#define TILE_E 8192   // 128*64 bf16 elements per tile (16 KB)
#define STAGE_E (2*TILE_E)
__device__ __forceinline__ void g2s_stage(
    const __nv_bfloat16* __restrict__ Aptr, const __nv_bfloat16* __restrict__ Bptr,
    __nv_bfloat16* sA, __nv_bfloat16* sB,
    int tid, int m0, int n0, int N, size_t K, size_t k0) {
#pragma unroll
    for (int c8 = 0; c8 < 8; c8++) {
        int c = tid + (c8 << 8);
        int r = (c & 1023) >> 3, kch = c & 7;
        int soff = r * 64 + ((kch ^ (r & 7)) << 3);
        if (c < 1024) {
            const void* g = Aptr + (size_t)(m0 + r) * K + k0 + kch * 8;
            uint32_t s = smem_u32(sA + soff);
            asm volatile("cp.async.cg.shared.global [%0], [%1], 16;" :: "r"(s), "l"(g));
        } else {
            int valid = (n0 + r) < N;
            const void* g = Bptr + (valid ? ((size_t)(n0 + r) * K + k0 + kch * 8) : 0);
            uint32_t s = smem_u32(sB + soff);
            int sz = valid ? 16 : 0;
            asm volatile("cp.async.cg.shared.global [%0], [%1], 16, %2;" :: "r"(s), "l"(g), "r"(sz));
        }
    }
}

__global__ __launch_bounds__(256, 2) void gemm_mma_splitk(
    const __nv_bfloat16* __restrict__ Ahi, const __nv_bfloat16* __restrict__ Alo,
    const __nv_bfloat16* __restrict__ Bthi, const __nv_bfloat16* __restrict__ Btlo,
    float* __restrict__ Cpart, int N, int K, int kchunk, int nphase,
    const float* __restrict__ bias, const float* __restrict__ bias2,
    float* __restrict__ Cout) {
    extern __shared__ __nv_bfloat16 sm[];

    const int tid  = threadIdx.x;
    const int warp = tid >> 5, lane = tid & 31;
    const int n0 = blockIdx.x * 128;
    const int m0 = blockIdx.y * 128;
    const int M  = gridDim.y * 128;
    const int z  = blockIdx.z;
    const size_t kbase = (size_t)z * kchunk;
    const int iters = kchunk >> 6;
    const int total = nphase * iters;

    const __nv_bfloat16* Ap[3] = {Ahi, Alo, Ahi};
    const __nv_bfloat16* Bp[3] = {Bthi, Bthi, Btlo};

    const int wm = warp >> 2;
    const int wn = warp & 3;
    const int g  = lane >> 2, tig = lane & 3;

    float acc[4][4][4];
#pragma unroll
    for (int mt = 0; mt < 4; mt++)
#pragma unroll
        for (int nt = 0; nt < 4; nt++)
#pragma unroll
            for (int e = 0; e < 4; e++) acc[mt][nt][e] = 0.0f;

    const int a_row = lane & 15;
    const int a_kc  = lane >> 4;
    const int b_row = (lane >> 4) * 8 + (lane & 7);
    const int b_kc  = (lane >> 3) & 1;

    g2s_stage(Ap[0], Bp[0], sm, sm + TILE_E, tid, m0, n0, N, K, kbase);
    asm volatile("cp.async.commit_group;" ::: "memory");
    if (total > 1) {
        int ph = 1 / iters, itk = 1 - ph * iters;
        g2s_stage(Ap[ph], Bp[ph], sm + STAGE_E, sm + STAGE_E + TILE_E,
                  tid, m0, n0, N, K, kbase + (size_t)itk * 64);
    }
    asm volatile("cp.async.commit_group;" ::: "memory");

    for (int j = 0; j < total; ++j) {
        asm volatile("cp.async.wait_group 1;" ::: "memory");
        __syncthreads();

        if (j + 2 < total) {
            int jn = j + 2;
            int ph = jn / iters, itk = jn - ph * iters;
            const int st2 = jn % 3;
            g2s_stage(Ap[ph], Bp[ph], sm + st2 * STAGE_E, sm + st2 * STAGE_E + TILE_E,
                      tid, m0, n0, N, K, kbase + (size_t)itk * 64);
        }
        asm volatile("cp.async.commit_group;" ::: "memory");

        const uint32_t sAb = smem_u32(sm) + (j % 3) * (STAGE_E * 2);
        const uint32_t sBb = sAb + TILE_E * 2;

#pragma unroll
        for (int ks = 0; ks < 4; ks++) {
            uint32_t a[4][4];
#pragma unroll
            for (int mt = 0; mt < 4; mt++) {
                int r = wm*64 + mt*16 + a_row;
                int kch = ks*2 + a_kc;
                uint32_t addr = sAb + r * 128 + (((kch ^ (r & 7))) << 4);
                asm volatile("ldmatrix.sync.aligned.m8n8.x4.shared.b16 {%0,%1,%2,%3}, [%4];"
                    : "=r"(a[mt][0]), "=r"(a[mt][1]), "=r"(a[mt][2]), "=r"(a[mt][3])
                    : "r"(addr));
            }
            uint32_t b[4][2];
#pragma unroll
            for (int np = 0; np < 2; np++) {
                int r = wn*32 + np*16 + b_row;
                int kch = ks*2 + b_kc;
                uint32_t addr = sBb + r * 128 + (((kch ^ (r & 7))) << 4);
                uint32_t r0, r1, r2, r3;
                asm volatile("ldmatrix.sync.aligned.m8n8.x4.shared.b16 {%0,%1,%2,%3}, [%4];"
                    : "=r"(r0), "=r"(r1), "=r"(r2), "=r"(r3) : "r"(addr));
                b[np*2+0][0] = r0; b[np*2+0][1] = r1;
                b[np*2+1][0] = r2; b[np*2+1][1] = r3;
            }
#pragma unroll
            for (int mt = 0; mt < 4; mt++)
#pragma unroll
                for (int nt = 0; nt < 4; nt++) {
                    asm volatile(
                        "mma.sync.aligned.m16n8k16.row.col.f32.bf16.bf16.f32 "
                        "{%0,%1,%2,%3}, {%4,%5,%6,%7}, {%8,%9}, {%0,%1,%2,%3};"
                        : "+f"(acc[mt][nt][0]), "+f"(acc[mt][nt][1]),
                          "+f"(acc[mt][nt][2]), "+f"(acc[mt][nt][3])
                        : "r"(a[mt][0]), "r"(a[mt][1]), "r"(a[mt][2]), "r"(a[mt][3]),
                          "r"(b[nt][0]), "r"(b[nt][1]));
                }
        }
        __syncthreads();
    }

    if (Cpart) {
        float* outz = Cpart + (size_t)z * M * N;
#pragma unroll
        for (int mt = 0; mt < 4; mt++)
#pragma unroll
            for (int nt = 0; nt < 4; nt++) {
                int row0 = m0 + wm*64 + mt*16 + g;
                int col  = n0 + wn*32 + nt*8 + tig*2;
                if (col < N) {
                    *(float2*)(outz + (size_t)row0 * N + col)
                        = make_float2(acc[mt][nt][0], acc[mt][nt][1]);
                    *(float2*)(outz + (size_t)(row0 + 8) * N + col)
                        = make_float2(acc[mt][nt][2], acc[mt][nt][3]);
                }
            }
    } else {
#pragma unroll
        for (int mt = 0; mt < 4; mt++)
#pragma unroll
            for (int nt = 0; nt < 4; nt++) {
                int row0 = m0 + wm*64 + mt*16 + g;
                int col  = n0 + wn*32 + nt*8 + tig*2;
                if (col < N) {
                    float b0v = bias[col]   + (bias2 ? bias2[col]   : 0.0f);
                    float b1v = bias[col+1] + (bias2 ? bias2[col+1] : 0.0f);
                    *(float2*)(Cout + (size_t)row0 * N + col)
                        = make_float2(acc[mt][nt][0] + b0v, acc[mt][nt][1] + b1v);
                    *(float2*)(Cout + (size_t)(row0 + 8) * N + col)
                        = make_float2(acc[mt][nt][2] + b0v, acc[mt][nt][3] + b1v);
                }
            }
    }
}

// ---------------- split-K reduce kernels ----------------
__global__ void reduce_hw2_kernel(const float* __restrict__ hb2) {
    int i = blockIdx.x * 256 + threadIdx.x;
    float s = hb2[i & (H16-1)];
#pragma unroll
    for (int zz = 0; zz < 4; zz++) s += d_gpart[(size_t)zz * (BQ*H16) + i];
    s = (s > 0.0f) ? s : s * SLOPE;
    __nv_bfloat16 h = __float2bfloat16(s);
    d_h2hi[i] = h;
    d_h2lo[i] = __float2bfloat16(s - __bfloat162float(h));
}

__global__ void reduce_hw3_kernel(const float* __restrict__ hb3) {
    int i = blockIdx.x * 256 + threadIdx.x;
    int col = i % TOT;
    float s = hb3[col];
#pragma unroll
    for (int zz = 0; zz < 8; zz++) s += d_gpart[(size_t)zz * (BQ*TOT) + i];
    d_allw[i] = s;
}

__global__ void fc1_reduce_kernel(const float* __restrict__ lb1) {
    int i = blockIdx.x * 256 + threadIdx.x;
    float s = lb1[i & 511];
#pragma unroll
    for (int zz = 0; zz < 32; zz++) s += d_gpart[(size_t)zz * (BQ*512) + i];
    d_fc1[i] = s;
}

// ---------------- persistent fused LSTM (f32x2 packed + float4 weight loads) ----------------
// ws layout: [k][uu(16)][gg(4)] -> thread tx reads float4 ws[k*64 + tx*4]
// hs layout: [k][34 pad]        -> float2 loads (136-byte row stride, 8-aligned)
__global__ __launch_bounds__(128) void lstm_fused_kernel() {
    extern __shared__ float lsm[];
    float* ws = lsm;               // [256][16][4]
    float* hs = lsm + 256*64;      // [256][34]

    const int tid = threadIdx.x;
    const int u0 = blockIdx.x * 16;
    const int b0 = blockIdx.y * 32;
    const int tx = tid & 15;
    const int ty = tid >> 4;

    for (int e = tid; e < 16384; e += 128) {
        int kk = e >> 6, c = e & 63;
        int uu = c >> 2, gg = c & 3;
        ws[e] = d_whhT[(size_t)kk * G4 + gg * HDIM + u0 + uu];
    }

    float creg[4] = {0.f, 0.f, 0.f, 0.f};

    for (int t = 0; t < SQ; t++) {
        uint64_t accp[2][4];   // batch-pair {bi0,bi1} / {bi2,bi3}, per gate
#pragma unroll
        for (int p = 0; p < 2; p++)
#pragma unroll
            for (int gg = 0; gg < 4; gg++) accp[p][gg] = 0ull;

        if (t > 0) {
            const float* hsrc = d_hbuf[(t-1) & 1];
            for (int e = tid; e < 8192; e += 128) {
                int bb = e >> 8, kk = e & 255;
                hs[kk*34 + bb] = __ldcg(&hsrc[(b0 + bb) * HDIM + kk]);
            }
            __syncthreads();
#pragma unroll 4
            for (int k = 0; k < 256; k++) {
                float4 wv = *(const float4*)&ws[k*64 + tx*4];
                uint64_t w0p = pk2(wv.x, wv.x);
                uint64_t w1p = pk2(wv.y, wv.y);
                uint64_t w2p = pk2(wv.z, wv.z);
                uint64_t w3p = pk2(wv.w, wv.w);
                float2 h01 = *(const float2*)&hs[k*34 + ty*4];
                float2 h23 = *(const float2*)&hs[k*34 + ty*4 + 2];
                uint64_t hp0 = pk2(h01.x, h01.y);
                uint64_t hp1 = pk2(h23.x, h23.y);
                FMA2(accp[0][0], hp0, w0p); FMA2(accp[0][1], hp0, w1p);
                FMA2(accp[0][2], hp0, w2p); FMA2(accp[0][3], hp0, w3p);
                FMA2(accp[1][0], hp1, w0p); FMA2(accp[1][1], hp1, w1p);
                FMA2(accp[1][2], hp1, w2p); FMA2(accp[1][3], hp1, w3p);
            }
        }

        float acc[4][4];
#pragma unroll
        for (int p = 0; p < 2; p++)
#pragma unroll
            for (int gg = 0; gg < 4; gg++)
                upk2(acc[p*2][gg], acc[p*2+1][gg], accp[p][gg]);

        float* hdst = d_hbuf[t & 1];
#pragma unroll
        for (int bi = 0; bi < 4; bi++) {
            int b = b0 + ty*4 + bi;
            const float* xg = d_Xg + ((size_t)t * BQ + b) * G4 + u0 + tx;
            float iv = sigmoidf_(acc[bi][0] + xg[0]);
            float fv = sigmoidf_(acc[bi][1] + xg[HDIM]);
            float gv = tanhf    (acc[bi][2] + xg[2*HDIM]);
            float ov = sigmoidf_(acc[bi][3] + xg[3*HDIM]);
            float c = fv * creg[bi] + iv * gv;
            creg[bi] = c;
            hdst[b * HDIM + u0 + tx] = ov * tanhf(c);
        }

        if (t < SQ - 1) {
            __syncthreads();
            __threadfence();
            if (tid == 0) {
                unsigned gen = atomicAdd(&d_barg, 0u);
                if (atomicAdd(&d_barc, 1u) == 127u) {
                    atomicExch(&d_barc, 0u);
                    __threadfence();
                    atomicExch(&d_barg, gen + 1u);
                } else {
                    while (atomicAdd(&d_barg, 0u) == gen) __nanosleep(64);
                }
                __threadfence();
            }
            __syncthreads();
        }
    }
}

// ---------------- conv1 (f32x2 packed) ----------------
__global__ void conv1_kernel(const float* __restrict__ images) {
    extern __shared__ float smf[];
    float* sin = smf;
    float* sw  = smf + 3*4096;
    float* sb  = sw + 432;
    const int b = blockIdx.x;
    const int tid = threadIdx.x;

    const float* ip = images + (size_t)b * 3 * 4096;
    for (int i = tid; i < 3*4096; i += 256) sin[i] = ip[i];
    const float* wp = d_allw + (size_t)b * TOT;
    for (int i = tid; i < 448; i += 256) {
        if (i < 432) sw[i] = wp[i]; else sb[i-432] = wp[i];
    }
    __syncthreads();

    for (int task = tid; task < 16*64*4; task += 256) {
        int oc = task >> 8;
        int y  = (task >> 2) & 63;
        int x0 = (task & 3) << 4;
        uint64_t accp[8];
#pragma unroll
        for (int p = 0; p < 8; p++) accp[p] = 0ull;

        for (int ic = 0; ic < 3; ic++) {
#pragma unroll
            for (int ky = 0; ky < 3; ky++) {
                int yy = y + ky - 1;
                if (yy < 0 || yy >= 64) continue;
                const float* row = sin + ic*4096 + yy*64;
                const float* w3  = sw + ((oc*3 + ic)*3 + ky)*3;
                float w0 = w3[0], w1 = w3[1], w2 = w3[2];
                float vals[18];
#pragma unroll
                for (int i = 0; i < 18; i++) {
                    int x = x0 + i - 1;
                    vals[i] = (x >= 0 && x < 64) ? row[x] : 0.0f;
                }
                uint64_t w0p = pk2(w0, w0), w1p = pk2(w1, w1), w2p = pk2(w2, w2);
#pragma unroll
                for (int p = 0; p < 8; p++) {
                    uint64_t v0 = pk2(vals[2*p],   vals[2*p+1]);
                    uint64_t v1 = pk2(vals[2*p+1], vals[2*p+2]);
                    uint64_t v2 = pk2(vals[2*p+2], vals[2*p+3]);
                    FMA2(accp[p], w0p, v0);
                    FMA2(accp[p], w1p, v1);
                    FMA2(accp[p], w2p, v2);
                }
            }
        }
        float bv = sb[oc];
        float* op = d_conv1o + (((size_t)b*16 + oc)*64 + y)*64 + x0;
#pragma unroll
        for (int p = 0; p < 8; p++) {
            float lo, hi;
            upk2(lo, hi, accp[p]);
            op[2*p]   = lo + bv;
            op[2*p+1] = hi + bv;
        }
    }
}

// ---------------- conv2 (f32x2 packed, writes bf16 hi/lo directly) ----------------
__global__ void conv2_kernel() {
    extern __shared__ float smf[];
    float* sin = smf;
    float* sw  = smf + 16*18*64;
    float* sb  = sw + 2304;
    const int b  = blockIdx.y;
    const int y0 = blockIdx.x * 16;
    const int tid = threadIdx.x;

    const float* ip = d_conv1o + (size_t)b * 16 * 4096;
    for (int i = tid; i < 16*18*64; i += 256) {
        int ic = i / (18*64);
        int r  = (i / 64) % 18;
        int x  = i & 63;
        int yy = y0 + r - 1;
        sin[i] = (yy >= 0 && yy < 64) ? ip[ic*4096 + yy*64 + x] : 0.0f;
    }
    const float* wp = d_allw + (size_t)b * TOT + 448;
    for (int i = tid; i < 2320; i += 256) {
        if (i < 2304) sw[i] = wp[i]; else sb[i-2304] = wp[i];
    }
    __syncthreads();

    const int pos = tid & 63;
    const int ocg = tid >> 6;
    const int y  = pos >> 2;
    const int x0 = (pos & 3) << 4;

    uint64_t accp[4][8];
#pragma unroll
    for (int o = 0; o < 4; o++)
#pragma unroll
        for (int p = 0; p < 8; p++) accp[o][p] = 0ull;

    for (int ic = 0; ic < 16; ic++) {
#pragma unroll
        for (int ky = 0; ky < 3; ky++) {
            const float* row = sin + (ic*18 + y + ky) * 64;
            float vals[18];
#pragma unroll
            for (int i = 0; i < 18; i++) {
                int x = x0 + i - 1;
                vals[i] = (x >= 0 && x < 64) ? row[x] : 0.0f;
            }
            uint64_t vp0[8], vp1[8], vp2[8];
#pragma unroll
            for (int p = 0; p < 8; p++) {
                vp0[p] = pk2(vals[2*p],   vals[2*p+1]);
                vp1[p] = pk2(vals[2*p+1], vals[2*p+2]);
                vp2[p] = pk2(vals[2*p+2], vals[2*p+3]);
            }
#pragma unroll
            for (int o = 0; o < 4; o++) {
                const float* w3 = sw + (((ocg*4 + o)*16 + ic)*3 + ky)*3;
                uint64_t w0p = pk2(w3[0], w3[0]);
                uint64_t w1p = pk2(w3[1], w3[1]);
                uint64_t w2p = pk2(w3[2], w3[2]);
#pragma unroll
                for (int p = 0; p < 8; p++) {
                    FMA2(accp[o][p], w0p, vp0[p]);
                    FMA2(accp[o][p], w1p, vp1[p]);
                    FMA2(accp[o][p], w2p, vp2[p]);
                }
            }
        }
    }
#pragma unroll
    for (int o = 0; o < 4; o++) {
        int oc = ocg*4 + o;
        float bv = sb[oc];
        size_t base = (((size_t)b*16 + oc)*64 + (y0 + y))*64 + x0;
#pragma unroll
        for (int p = 0; p < 8; p++) {
            float lo, hi;
            upk2(lo, hi, accp[o][p]);
            float v0 = lo + bv, v1 = hi + bv;
            __nv_bfloat16 h0 = __float2bfloat16(v0);
            __nv_bfloat16 h1 = __float2bfloat16(v1);
            d_Ahi[base + 2*p]   = h0;
            d_Ahi[base + 2*p+1] = h1;
            d_Alo[base + 2*p]   = __float2bfloat16(v0 - __bfloat162float(h0));
            d_Alo[base + 2*p+1] = __float2bfloat16(v1 - __bfloat162float(h1));
        }
    }
}

// ---------------- fused fc2 + fc3 (unchanged) ----------------
__global__ void fc23_kernel(const float* __restrict__ lw2, const float* __restrict__ lb2,
                            const float* __restrict__ lw3, const float* __restrict__ lb3,
                            float* __restrict__ out) {
    const int b = blockIdx.x;
    const int j = threadIdx.x;
    const float* a = d_fc1 + (size_t)b * 512;
    float acc = lb2[j];
#pragma unroll 4
    for (int k = 0; k < 512; k++)
        acc += fmaxf(a[k], 0.0f) * lw2[(size_t)k*64 + j];
    acc = fmaxf(acc, 0.0f);
    __shared__ float h[64];
    h[j] = acc;
    __syncthreads();
    if (j < 2) {
        float s = lb3[j];
#pragma unroll
        for (int q = 0; q < 64; q++) s += h[q] * lw3[q*2 + j];
        out[b*2 + j] = s;
    }
}

// ---------------- launch ----------------
extern "C" void kernel_launch(void* const* d_in, const int* in_sizes, int n_in,
                              void* d_out, int out_size) {
    const int*   questions = (const int*)  d_in[0];
    const float* images    = (const float*)d_in[1];
    const float* emb       = (const float*)d_in[2];
    const float* w_ih      = (const float*)d_in[3];
    const float* w_hh      = (const float*)d_in[4];
    const float* b_ih      = (const float*)d_in[5];
    const float* b_hh      = (const float*)d_in[6];
    const float* hw1       = (const float*)d_in[7];
    const float* hb1       = (const float*)d_in[8];
    const float* hw2       = (const float*)d_in[9];
    const float* hb2       = (const float*)d_in[10];
    const float* hw3       = (const float*)d_in[11];
    const float* hb3       = (const float*)d_in[12];
    const float* lw1       = (const float*)d_in[13];
    const float* lb1       = (const float*)d_in[14];
    const float* lw2       = (const float*)d_in[15];
    const float* lb2       = (const float*)d_in[16];
    const float* lw3       = (const float*)d_in[17];
    const float* lb3       = (const float*)d_in[18];
    float* out = (float*)d_out;

    // __device__ symbols are NOT valid device pointers in host code: fetch real addresses.
    float *p_Xg, *p_whhT, *p_hbuf, *p_h1, *p_gpart;
    __nv_bfloat16 *p_Xehl, *p_Bwih, *p_Ahi, *p_Alo, *p_Bthi, *p_Btlo,
                  *p_Bt2hi, *p_Bt2lo, *p_Bt3hi, *p_Bt3lo,
                  *p_h1hi, *p_h1lo, *p_h2hi, *p_h2lo;
    cudaGetSymbolAddress((void**)&p_Xg,    d_Xg);
    cudaGetSymbolAddress((void**)&p_whhT,  d_whhT);
    cudaGetSymbolAddress((void**)&p_hbuf,  d_hbuf);
    cudaGetSymbolAddress((void**)&p_h1,    d_h1);
    cudaGetSymbolAddress((void**)&p_gpart, d_gpart);
    cudaGetSymbolAddress((void**)&p_Xehl,  d_Xehl);
    cudaGetSymbolAddress((void**)&p_Bwih,  d_Bwih);
    cudaGetSymbolAddress((void**)&p_Ahi,   d_Ahi);
    cudaGetSymbolAddress((void**)&p_Alo,   d_Alo);
    cudaGetSymbolAddress((void**)&p_Bthi,  d_Bthi);
    cudaGetSymbolAddress((void**)&p_Btlo,  d_Btlo);
    cudaGetSymbolAddress((void**)&p_Bt2hi, d_Bt2hi);
    cudaGetSymbolAddress((void**)&p_Bt2lo, d_Bt2lo);
    cudaGetSymbolAddress((void**)&p_Bt3hi, d_Bt3hi);
    cudaGetSymbolAddress((void**)&p_Bt3lo, d_Bt3lo);
    cudaGetSymbolAddress((void**)&p_h1hi,  d_h1hi);
    cudaGetSymbolAddress((void**)&p_h1lo,  d_h1lo);
    cudaGetSymbolAddress((void**)&p_h2hi,  d_h2hi);
    cudaGetSymbolAddress((void**)&p_h2lo,  d_h2lo);

    const int conv1_smem = (3*4096 + 448) * 4;
    const int conv2_smem = (16*18*64 + 2320) * 4;
    const int mma_smem   = 3 * STAGE_E * 2;          // 98304 B
    const int lstm_smem  = (16384 + 256*34) * 4;     // 100352 B
    cudaFuncSetAttribute(conv1_kernel, cudaFuncAttributeMaxDynamicSharedMemorySize, conv1_smem);
    cudaFuncSetAttribute(conv2_kernel, cudaFuncAttributeMaxDynamicSharedMemorySize, conv2_smem);
    cudaFuncSetAttribute(gemm_mma_splitk, cudaFuncAttributeMaxDynamicSharedMemorySize, mma_smem);
    cudaFuncSetAttribute(lstm_fused_kernel, cudaFuncAttributeMaxDynamicSharedMemorySize, lstm_smem);

    // 1) transpose w_hh (fp32, for LSTM smem)
    transpose_kernel<<<(G4*HDIM + 255)/256, 256>>>(w_hh, p_whhT, G4, HDIM);
    // 2) embedding gather -> bf16 concat-K triple
    gather_hl_kernel<<<(SQ*BQ*EDIM + 255)/256, 256>>>(questions, emb);
    // 3) w_ih -> bf16 triple
    convert_wih_kernel<<<(G4*EDIM + 255)/256, 256>>>(w_ih);
    // 4) Xg = Xe @ w_ih^T + b_ih + b_hh via HMMA concat-K (5120 x 1024, K'=384)
    gemm_mma_splitk<<<dim3(G4/128, (SQ*BQ)/128, 1), 256, mma_smem>>>(
        p_Xehl, nullptr, p_Bwih, nullptr, nullptr, G4, 384, 384, 1, b_ih, b_hh, p_Xg);
    // 5) full LSTM recurrence in ONE persistent kernel (final h -> d_hbuf[1])
    lstm_fused_kernel<<<dim3(16, 8), 128, lstm_smem>>>();
    // 6) weight transconversions for the big GEMMs
    transconv_kernel<<<dim3(FLAT/32, 512/32), 256>>>(lw1, p_Bthi, p_Btlo, FLAT, 512);
    transconv_kernel<<<dim3(G4/32, H16/32), 256>>>(hw2, p_Bt2hi, p_Bt2lo, G4, H16);
    transconv_kernel<<<dim3(H16/32, (TOT+31)/32), 256>>>(hw3, p_Bt3hi, p_Bt3lo, H16, TOT);
    // 7) hw1 fp32 (K=256 too small for HMMA payoff) + hi/lo convert
    gemm_nn_kernel<1, false><<<dim3(G4/64, BQ/64), 256>>>(
        p_hbuf + BQ*HDIM, hw1, hb1, nullptr, p_h1, BQ, G4, HDIM);
    convert_hilo_kernel<<<BQ*G4/1024, 256>>>(p_h1, p_h1hi, p_h1lo);
    // 8) hw2 (256 x 4096, K=1024): 4-way K-split, 3 phases fused in-kernel
    gemm_mma_splitk<<<dim3(H16/128, BQ/128, 4), 256, mma_smem>>>(
        p_h1hi, p_h1lo, p_Bt2hi, p_Bt2lo, p_gpart, H16, G4, G4/4, 3,
        nullptr, nullptr, nullptr);
    reduce_hw2_kernel<<<BQ*H16/256, 256>>>(hb2);
    // 9) hw3 (256 x 2768, K=4096): 8-way K-split, 3 phases fused
    gemm_mma_splitk<<<dim3((TOT+127)/128, BQ/128, 8), 256, mma_smem>>>(
        p_h2hi, p_h2lo, p_Bt3hi, p_Bt3lo, p_gpart, TOT, H16, H16/8, 3,
        nullptr, nullptr, nullptr);
    reduce_hw3_kernel<<<BQ*TOT/256, 256>>>(hb3);
    // 10) per-sample convs (f32x2 packed; conv2 emits fc1's bf16 hi/lo A directly)
    conv1_kernel<<<BQ, 256, conv1_smem>>>(images);
    conv2_kernel<<<dim3(4, BQ), 256, conv2_smem>>>();
    // 11) fc1 (256 x 512, K=65536): 32-way K-split, 3 phases fused
    gemm_mma_splitk<<<dim3(512/128, BQ/128, 32), 256, mma_smem>>>(
        p_Ahi, p_Alo, p_Bthi, p_Btlo, p_gpart, 512, FLAT, FLAT/32, 3,
        nullptr, nullptr, nullptr);
    fc1_reduce_kernel<<<(BQ*512 + 255)/256, 256>>>(lb1);
    // 12) fused fc2 (relu) + fc3
    fc23_kernel<<<BQ, 64>>>(lw2, lb2, lw3, lb3, out);
}